// round 3
// baseline (speedup 1.0000x reference)
#include <cuda_runtime.h>
#include <math.h>

#define BTOT   65536
#define DIN    256
#define HDIM   64
#define ADIM   32
#define NACT   14
#define NS     8
#define BM     64
#define PT     68        // pitch for 64-wide tiles (row-major), 16B-aligned rows
#define PH     104       // pitch for ho_s rows: [0..63]=h_out, [64..95]=xatt
#define PQ     104       // pitch for qkv rows
#define NTHREADS 256

typedef unsigned long long ull;

// ---- persistent pair-packed weights (k-pairs innermost) ----
__device__ __align__(16) float g_encP[128 * 128];      // [k2][j*2+p], k2<128, j<64
__device__ __align__(16) float g_WxP[3 * 32 * 128];    // [g][k2][j*2+p], k2<32
__device__ __align__(16) float g_WhP[3 * 32 * 128];
__device__ __align__(16) float g_qkvP[32 * 192];       // [k2][j*2+p], j<96 (q|k|v)
__device__ __align__(16) float g_decP[14 * 96];        // [c][k2*2+p], k2<48

__global__ void setup_kernel(const float* __restrict__ encW,
                             const float* __restrict__ Wih,
                             const float* __restrict__ Whh,
                             const float* __restrict__ qW,
                             const float* __restrict__ kW,
                             const float* __restrict__ vW,
                             const float* __restrict__ decW)
{
    const int stride = gridDim.x * blockDim.x;
    const int t0 = blockIdx.x * blockDim.x + threadIdx.x;
    for (int idx = t0; idx < 128 * 128; idx += stride) {
        int k2 = idx >> 7, rem = idx & 127, j = rem >> 1, p = rem & 1;
        g_encP[idx] = encW[(2 * k2 + p) * HDIM + j];
    }
    for (int idx = t0; idx < 3 * 32 * 128; idx += stride) {
        int g = idx / 4096, rem = idx & 4095;
        int k2 = rem >> 7, r2 = rem & 127, j = r2 >> 1, p = r2 & 1;
        g_WxP[idx] = Wih[(g * 64 + j) * HDIM + 2 * k2 + p];
        g_WhP[idx] = Whh[(g * 64 + j) * HDIM + 2 * k2 + p];
    }
    for (int idx = t0; idx < 32 * 192; idx += stride) {
        int k2 = idx / 192, r = idx - k2 * 192, j = r >> 1, p = r & 1;
        int row = 2 * k2 + p;
        float v;
        if (j < 32)      v = qW[row * 32 + j];
        else if (j < 64) v = kW[row * 32 + (j - 32)];
        else             v = vW[row * 32 + (j - 64)];
        g_qkvP[idx] = v;
    }
    for (int idx = t0; idx < 14 * 96; idx += stride) {
        int c = idx / 96, r = idx - c * 96, k2 = r >> 1, p = r & 1;
        g_decP[idx] = decW[(2 * k2 + p) * NACT + c];
    }
}

// ---------------- f32x2 helpers ----------------
__device__ __forceinline__ void ffma2(ull& acc, ull a, ull b) {
    asm("fma.rn.f32x2 %0, %1, %2, %0;" : "+l"(acc) : "l"(a), "l"(b));
}
__device__ __forceinline__ float hsum2(ull v) {
    float2 r;
    asm("mov.b64 {%0, %1}, %2;" : "=f"(r.x), "=f"(r.y) : "l"(v));
    return r.x + r.y;
}
__device__ __forceinline__ unsigned saddr(const void* p) {
    return (unsigned)__cvta_generic_to_shared(p);
}
__device__ __forceinline__ float tanh_fast(float x) {
    float r; asm("tanh.approx.f32 %0, %1;" : "=f"(r) : "f"(x)); return r;
}
__device__ __forceinline__ float sigmoid_fast(float s) {
    return fmaf(tanh_fast(0.5f * s), 0.5f, 0.5f);
}

// fused gate GEMM: acc += x·WxP[g] + h·WhP[g]   (K=64, 4x4 output tile)
__device__ __forceinline__ void gate_fused(const float* __restrict__ x_s,
                                           const float* __restrict__ h_s,
                                           const float* __restrict__ Wx,
                                           const float* __restrict__ Wh,
                                           int r0, int c0, ull acc[4][4])
{
#pragma unroll 4
    for (int kk = 0; kk < HDIM; kk += 4) {
        const int k2 = kk >> 1;
        const ulonglong2 wx0 = *reinterpret_cast<const ulonglong2*>(&Wx[(k2 + 0) * 128 + c0 * 2]);
        const ulonglong2 wx0b = *reinterpret_cast<const ulonglong2*>(&Wx[(k2 + 0) * 128 + c0 * 2 + 4]);
        const ulonglong2 wx1 = *reinterpret_cast<const ulonglong2*>(&Wx[(k2 + 1) * 128 + c0 * 2]);
        const ulonglong2 wx1b = *reinterpret_cast<const ulonglong2*>(&Wx[(k2 + 1) * 128 + c0 * 2 + 4]);
        const ulonglong2 wh0 = *reinterpret_cast<const ulonglong2*>(&Wh[(k2 + 0) * 128 + c0 * 2]);
        const ulonglong2 wh0b = *reinterpret_cast<const ulonglong2*>(&Wh[(k2 + 0) * 128 + c0 * 2 + 4]);
        const ulonglong2 wh1 = *reinterpret_cast<const ulonglong2*>(&Wh[(k2 + 1) * 128 + c0 * 2]);
        const ulonglong2 wh1b = *reinterpret_cast<const ulonglong2*>(&Wh[(k2 + 1) * 128 + c0 * 2 + 4]);
        const ull wx0v[4] = {wx0.x, wx0.y, wx0b.x, wx0b.y};
        const ull wx1v[4] = {wx1.x, wx1.y, wx1b.x, wx1b.y};
        const ull wh0v[4] = {wh0.x, wh0.y, wh0b.x, wh0b.y};
        const ull wh1v[4] = {wh1.x, wh1.y, wh1b.x, wh1b.y};
#pragma unroll
        for (int i = 0; i < 4; i++) {
            const ulonglong2 xv = *reinterpret_cast<const ulonglong2*>(&x_s[(r0 + i) * PT + kk]);
            const ulonglong2 hv = *reinterpret_cast<const ulonglong2*>(&h_s[(r0 + i) * PT + kk]);
#pragma unroll
            for (int j = 0; j < 4; j++) {
                ffma2(acc[i][j], xv.x, wx0v[j]);
                ffma2(acc[i][j], xv.y, wx1v[j]);
                ffma2(acc[i][j], hv.x, wh0v[j]);
                ffma2(acc[i][j], hv.y, wh1v[j]);
            }
        }
    }
}

// single-operand gate GEMM: acc += a·W   (K=64)
__device__ __forceinline__ void gate_single(const float* __restrict__ a_s,
                                            const float* __restrict__ W,
                                            int r0, int c0, ull acc[4][4])
{
#pragma unroll 4
    for (int kk = 0; kk < HDIM; kk += 4) {
        const int k2 = kk >> 1;
        const ulonglong2 w0 = *reinterpret_cast<const ulonglong2*>(&W[(k2 + 0) * 128 + c0 * 2]);
        const ulonglong2 w0b = *reinterpret_cast<const ulonglong2*>(&W[(k2 + 0) * 128 + c0 * 2 + 4]);
        const ulonglong2 w1 = *reinterpret_cast<const ulonglong2*>(&W[(k2 + 1) * 128 + c0 * 2]);
        const ulonglong2 w1b = *reinterpret_cast<const ulonglong2*>(&W[(k2 + 1) * 128 + c0 * 2 + 4]);
        const ull w0v[4] = {w0.x, w0.y, w0b.x, w0b.y};
        const ull w1v[4] = {w1.x, w1.y, w1b.x, w1b.y};
#pragma unroll
        for (int i = 0; i < 4; i++) {
            const ulonglong2 av = *reinterpret_cast<const ulonglong2*>(&a_s[(r0 + i) * PT + kk]);
#pragma unroll
            for (int j = 0; j < 4; j++) {
                ffma2(acc[i][j], av.x, w0v[j]);
                ffma2(acc[i][j], av.y, w1v[j]);
            }
        }
    }
}

__global__ void __launch_bounds__(NTHREADS, 2)
fused_kernel(const float* __restrict__ obs,
             const float* __restrict__ hid,
             const float* __restrict__ encb,
             const float* __restrict__ bih,
             const float* __restrict__ bhh,
             const float* __restrict__ vb,
             const float* __restrict__ decb,
             float* __restrict__ outp,
             float* __restrict__ houtp)
{
    extern __shared__ float sm[];
    float* Abuf0 = sm;                 // [64][PT] obs tile (double buffer)
    float* Abuf1 = sm + 4352;
    float* x_s   = sm + 8704;          // [64][PT] encoder output
    float* h_s   = sm + 13056;         // [64][PT] hidden_state
    float* ho_s  = sm + 17408;         // [64][PH] h_out | xatt
    float* qkv_s = sm;                 // [64][PQ] overlays A buffers (dead)

    const int tid  = threadIdx.x;
    const int trow = tid >> 4;
    const int tcol = tid & 15;
    const int r0 = trow * 4;
    const int c0 = tcol * 4;
    const int rowbase = blockIdx.x * BM;

    // ---- prefetch obs tile 0 via cp.async ----
    {
#pragma unroll
        for (int c = 0; c < 4; c++) {
            int chunk = tid + c * 256;               // 1024 chunks of 16B
            int row = chunk >> 4, off = (chunk & 15) * 4;
            const float* src = obs + (size_t)(rowbase + row) * DIN + off;
            unsigned d = saddr(&Abuf0[row * PT + off]);
            asm volatile("cp.async.cg.shared.global [%0], [%1], 16;" :: "r"(d), "l"(src));
        }
        asm volatile("cp.async.commit_group;");
    }

    // ---- load hidden_state tile (row-major, float4) ----
    for (int v = tid; v < BM * 16; v += NTHREADS) {
        int r = v >> 4, cq = (v & 15) * 4;
        *reinterpret_cast<float4*>(&h_s[r * PT + cq]) =
            *reinterpret_cast<const float4*>(&hid[(size_t)(rowbase + r) * HDIM + cq]);
    }

    // ---------------- encoder: x = relu(obs @ enc_W + enc_b) ----------------
    {
        ull acc[4][4];
#pragma unroll
        for (int i = 0; i < 4; i++)
#pragma unroll
            for (int j = 0; j < 4; j++) acc[i][j] = 0;

#pragma unroll
        for (int kt = 0; kt < 4; kt++) {
            __syncthreads();
            if (kt < 3) {
                float* dst = ((kt + 1) & 1) ? Abuf1 : Abuf0;
#pragma unroll
                for (int c = 0; c < 4; c++) {
                    int chunk = tid + c * 256;
                    int row = chunk >> 4, off = (chunk & 15) * 4;
                    const float* src = obs + (size_t)(rowbase + row) * DIN + (kt + 1) * 64 + off;
                    unsigned d = saddr(&dst[row * PT + off]);
                    asm volatile("cp.async.cg.shared.global [%0], [%1], 16;" :: "r"(d), "l"(src));
                }
                asm volatile("cp.async.commit_group;");
                asm volatile("cp.async.wait_group 1;");
            } else {
                asm volatile("cp.async.wait_group 0;");
            }
            __syncthreads();

            const float* Ac = (kt & 1) ? Abuf1 : Abuf0;
#pragma unroll 4
            for (int kk = 0; kk < 64; kk += 4) {
                const int k2 = (kt * 64 + kk) >> 1;
                const ulonglong2 w0 = *reinterpret_cast<const ulonglong2*>(&g_encP[(k2 + 0) * 128 + c0 * 2]);
                const ulonglong2 w0b = *reinterpret_cast<const ulonglong2*>(&g_encP[(k2 + 0) * 128 + c0 * 2 + 4]);
                const ulonglong2 w1 = *reinterpret_cast<const ulonglong2*>(&g_encP[(k2 + 1) * 128 + c0 * 2]);
                const ulonglong2 w1b = *reinterpret_cast<const ulonglong2*>(&g_encP[(k2 + 1) * 128 + c0 * 2 + 4]);
                const ull w0v[4] = {w0.x, w0.y, w0b.x, w0b.y};
                const ull w1v[4] = {w1.x, w1.y, w1b.x, w1b.y};
#pragma unroll
                for (int i = 0; i < 4; i++) {
                    const ulonglong2 xv = *reinterpret_cast<const ulonglong2*>(&Ac[(r0 + i) * PT + kk]);
#pragma unroll
                    for (int j = 0; j < 4; j++) {
                        ffma2(acc[i][j], xv.x, w0v[j]);
                        ffma2(acc[i][j], xv.y, w1v[j]);
                    }
                }
            }
        }
        const float4 b4 = *reinterpret_cast<const float4*>(&encb[c0]);
        const float bv[4] = {b4.x, b4.y, b4.z, b4.w};
#pragma unroll
        for (int i = 0; i < 4; i++) {
            float4 o;
            o.x = fmaxf(hsum2(acc[i][0]) + bv[0], 0.f);
            o.y = fmaxf(hsum2(acc[i][1]) + bv[1], 0.f);
            o.z = fmaxf(hsum2(acc[i][2]) + bv[2], 0.f);
            o.w = fmaxf(hsum2(acc[i][3]) + bv[3], 0.f);
            *reinterpret_cast<float4*>(&x_s[(r0 + i) * PT + c0]) = o;
        }
    }
    __syncthreads();

    // ---------------- GRU cell ----------------
    {
        float rg[4][4], zg[4][4], rn[4][4];
        ull acc[4][4];

        // r gate (fused x+h)
#pragma unroll
        for (int i = 0; i < 4; i++)
#pragma unroll
            for (int j = 0; j < 4; j++) acc[i][j] = 0;
        gate_fused(x_s, h_s, g_WxP, g_WhP, r0, c0, acc);
        {
            const float4 bx = *reinterpret_cast<const float4*>(&bih[c0]);
            const float4 bh = *reinterpret_cast<const float4*>(&bhh[c0]);
            const float bs[4] = {bx.x + bh.x, bx.y + bh.y, bx.z + bh.z, bx.w + bh.w};
#pragma unroll
            for (int i = 0; i < 4; i++)
#pragma unroll
                for (int j = 0; j < 4; j++)
                    rg[i][j] = sigmoid_fast(hsum2(acc[i][j]) + bs[j]);
        }

        // z gate (fused x+h)
#pragma unroll
        for (int i = 0; i < 4; i++)
#pragma unroll
            for (int j = 0; j < 4; j++) acc[i][j] = 0;
        gate_fused(x_s, h_s, g_WxP + 4096, g_WhP + 4096, r0, c0, acc);
        {
            const float4 bx = *reinterpret_cast<const float4*>(&bih[64 + c0]);
            const float4 bh = *reinterpret_cast<const float4*>(&bhh[64 + c0]);
            const float bs[4] = {bx.x + bh.x, bx.y + bh.y, bx.z + bh.z, bx.w + bh.w};
#pragma unroll
            for (int i = 0; i < 4; i++)
#pragma unroll
                for (int j = 0; j < 4; j++)
                    zg[i][j] = sigmoid_fast(hsum2(acc[i][j]) + bs[j]);
        }

        // n gate: hn pass, then xn pass
#pragma unroll
        for (int i = 0; i < 4; i++)
#pragma unroll
            for (int j = 0; j < 4; j++) acc[i][j] = 0;
        gate_single(h_s, g_WhP + 8192, r0, c0, acc);
        {
            const float4 bh = *reinterpret_cast<const float4*>(&bhh[128 + c0]);
            const float bhv[4] = {bh.x, bh.y, bh.z, bh.w};
#pragma unroll
            for (int i = 0; i < 4; i++)
#pragma unroll
                for (int j = 0; j < 4; j++)
                    rn[i][j] = rg[i][j] * (hsum2(acc[i][j]) + bhv[j]);
        }
#pragma unroll
        for (int i = 0; i < 4; i++)
#pragma unroll
            for (int j = 0; j < 4; j++) acc[i][j] = 0;
        gate_single(x_s, g_WxP + 8192, r0, c0, acc);
        {
            const float4 bx = *reinterpret_cast<const float4*>(&bih[128 + c0]);
            const float bxv[4] = {bx.x, bx.y, bx.z, bx.w};
#pragma unroll
            for (int i = 0; i < 4; i++) {
                float4 o;
                float* op = &o.x;
#pragma unroll
                for (int j = 0; j < 4; j++) {
                    float nn = tanh_fast(hsum2(acc[i][j]) + bxv[j] + rn[i][j]);
                    float hp = h_s[(r0 + i) * PT + c0 + j];
                    op[j] = (1.f - zg[i][j]) * nn + zg[i][j] * hp;
                }
                *reinterpret_cast<float4*>(&ho_s[(r0 + i) * PH + c0]) = o;
            }
        }
    }
    __syncthreads();

    // ---------------- q|k|v = h_out @ [qW|kW|vW]  (N=96, tile 4x6) ----------
    {
        const int cq = tcol * 6;
        ull acc[4][6];
#pragma unroll
        for (int i = 0; i < 4; i++)
#pragma unroll
            for (int m = 0; m < 6; m++) acc[i][m] = 0;

#pragma unroll 4
        for (int kk = 0; kk < HDIM; kk += 4) {
            const int k2 = kk >> 1;
            const ulonglong2 wa0 = *reinterpret_cast<const ulonglong2*>(&g_qkvP[(k2 + 0) * 192 + cq * 2]);
            const ulonglong2 wa1 = *reinterpret_cast<const ulonglong2*>(&g_qkvP[(k2 + 0) * 192 + cq * 2 + 4]);
            const ulonglong2 wa2 = *reinterpret_cast<const ulonglong2*>(&g_qkvP[(k2 + 0) * 192 + cq * 2 + 8]);
            const ulonglong2 wb0 = *reinterpret_cast<const ulonglong2*>(&g_qkvP[(k2 + 1) * 192 + cq * 2]);
            const ulonglong2 wb1 = *reinterpret_cast<const ulonglong2*>(&g_qkvP[(k2 + 1) * 192 + cq * 2 + 4]);
            const ulonglong2 wb2 = *reinterpret_cast<const ulonglong2*>(&g_qkvP[(k2 + 1) * 192 + cq * 2 + 8]);
            const ull w0v[6] = {wa0.x, wa0.y, wa1.x, wa1.y, wa2.x, wa2.y};
            const ull w1v[6] = {wb0.x, wb0.y, wb1.x, wb1.y, wb2.x, wb2.y};
#pragma unroll
            for (int i = 0; i < 4; i++) {
                const ulonglong2 hv = *reinterpret_cast<const ulonglong2*>(&ho_s[(r0 + i) * PH + kk]);
#pragma unroll
                for (int m = 0; m < 6; m++) {
                    ffma2(acc[i][m], hv.x, w0v[m]);
                    ffma2(acc[i][m], hv.y, w1v[m]);
                }
            }
        }
#pragma unroll
        for (int i = 0; i < 4; i++)
#pragma unroll
            for (int m = 0; m < 6; m++) {
                int cg = cq + m;
                float v = hsum2(acc[i][m]);
                if (cg >= 64) v = fmaxf(v + vb[cg - 64], 0.f);
                qkv_s[(r0 + i) * PQ + cg] = v;
            }

        // h_out writeback (coalesced float4) — independent of attention
        for (int v = tid; v < BM * 16; v += NTHREADS) {
            int r = v >> 4, cc = (v & 15) * 4;
            *reinterpret_cast<float4*>(&houtp[(size_t)(rowbase + r) * HDIM + cc]) =
                *reinterpret_cast<const float4*>(&ho_s[r * PH + cc]);
        }
    }
    __syncthreads();

    // ---------------- exclude-self attention (8 groups of 8 rows) -----------
    if (tid < BM) {
        const int ii = tid & 7;
        const int base = tid & ~7;
        float q[ADIM];
#pragma unroll
        for (int a4 = 0; a4 < 8; a4++) {
            float4 t = *reinterpret_cast<const float4*>(&qkv_s[tid * PQ + a4 * 4]);
            q[a4 * 4 + 0] = t.x; q[a4 * 4 + 1] = t.y; q[a4 * 4 + 2] = t.z; q[a4 * 4 + 3] = t.w;
        }
        float sc[NS]; float mx = -1e30f;
#pragma unroll
        for (int j = 0; j < NS; j++) {
            float s = 0.f;
#pragma unroll
            for (int a4 = 0; a4 < 8; a4++) {
                float4 t = *reinterpret_cast<const float4*>(&qkv_s[(base + j) * PQ + 32 + a4 * 4]);
                s = fmaf(q[a4 * 4 + 0], t.x, s); s = fmaf(q[a4 * 4 + 1], t.y, s);
                s = fmaf(q[a4 * 4 + 2], t.z, s); s = fmaf(q[a4 * 4 + 3], t.w, s);
            }
            s *= 0.17677669529663689f;
            if (j == ii) s = -1e9f;
            sc[j] = s; mx = fmaxf(mx, s);
        }
        float sum = 0.f;
#pragma unroll
        for (int j = 0; j < NS; j++) { sc[j] = __expf(sc[j] - mx); sum += sc[j]; }
        const float inv = __fdividef(1.f, sum);
        float xa[ADIM];
#pragma unroll
        for (int a = 0; a < ADIM; a++) xa[a] = 0.f;
#pragma unroll
        for (int j = 0; j < NS; j++) {
            float w = sc[j] * inv;
#pragma unroll
            for (int a4 = 0; a4 < 8; a4++) {
                float4 t = *reinterpret_cast<const float4*>(&qkv_s[(base + j) * PQ + 64 + a4 * 4]);
                xa[a4 * 4 + 0] = fmaf(w, t.x, xa[a4 * 4 + 0]);
                xa[a4 * 4 + 1] = fmaf(w, t.y, xa[a4 * 4 + 1]);
                xa[a4 * 4 + 2] = fmaf(w, t.z, xa[a4 * 4 + 2]);
                xa[a4 * 4 + 3] = fmaf(w, t.w, xa[a4 * 4 + 3]);
            }
        }
#pragma unroll
        for (int a4 = 0; a4 < 8; a4++) {
            float4 o = make_float4(xa[a4 * 4], xa[a4 * 4 + 1], xa[a4 * 4 + 2], xa[a4 * 4 + 3]);
            *reinterpret_cast<float4*>(&ho_s[tid * PH + 64 + a4 * 4]) = o;
        }
    }
    __syncthreads();

    // ---------------- decoder: out = [h_out|xatt] @ decW + decb -------------
    for (int idx = tid; idx < BM * NACT; idx += NTHREADS) {
        int r = idx / NACT;
        int c = idx - r * NACT;
        const ull* hp = reinterpret_cast<const ull*>(&ho_s[r * PH]);
        const ull* wp = reinterpret_cast<const ull*>(&g_decP[c * 96]);
        ull acc = 0;
#pragma unroll 8
        for (int kp = 0; kp < 48; kp++) ffma2(acc, hp[kp], wp[kp]);
        outp[(size_t)(rowbase + r) * NACT + c] = hsum2(acc) + decb[c];
    }
}

extern "C" void kernel_launch(void* const* d_in, const int* in_sizes, int n_in,
                              void* d_out, int out_size)
{
    (void)in_sizes; (void)n_in; (void)out_size;
    const float* obs  = (const float*)d_in[0];
    const float* hid  = (const float*)d_in[1];
    const float* encW = (const float*)d_in[2];
    const float* encb = (const float*)d_in[3];
    const float* Wih  = (const float*)d_in[4];
    const float* Whh  = (const float*)d_in[5];
    const float* bih  = (const float*)d_in[6];
    const float* bhh  = (const float*)d_in[7];
    const float* qW   = (const float*)d_in[8];
    const float* kW   = (const float*)d_in[9];
    const float* vW   = (const float*)d_in[10];
    const float* vb   = (const float*)d_in[11];
    const float* decW = (const float*)d_in[12];
    const float* decb = (const float*)d_in[13];

    float* outp  = (float*)d_out;                 // [B, 14]
    float* houtp = outp + (size_t)BTOT * NACT;    // [B, 64]

    setup_kernel<<<64, 256>>>(encW, Wih, Whh, qW, kW, vW, decW);

    const int smem_bytes = 24064 * sizeof(float); // 96,256 B
    cudaFuncSetAttribute(fused_kernel,
                         cudaFuncAttributeMaxDynamicSharedMemorySize, smem_bytes);
    fused_kernel<<<BTOT / BM, NTHREADS, smem_bytes>>>(
        obs, hid, encb, bih, bhh, vb, decb, outp, houtp);
}

// round 4
// speedup vs baseline: 1.1910x; 1.1910x over previous
#include <cuda_runtime.h>
#include <math.h>

#define BTOT   65536
#define DIN    256
#define HDIM   64
#define ADIM   32
#define NACT   14
#define NS     8
#define BM     64
#define PT     68        // pitch for 64-wide tiles (row-major), 16B-aligned rows
#define PH     100       // pitch for ho_s rows: [0..63]=h_out, [64..95]=xatt
#define PQ     100       // pitch for qkv rows
#define NTHREADS 256

typedef unsigned long long ull;

// ---- persistent repacked weights (j-adjacent pairs, R2 layout) ----
__device__ __align__(16) float g_WihT[HDIM * 3 * HDIM];   // [k=64][j=192]
__device__ __align__(16) float g_WhhT[HDIM * 3 * HDIM];   // [k=64][j=192]
__device__ __align__(16) float g_qkvW[HDIM * 96];         // [k=64][q|k|v = 96]
__device__ __align__(16) float g_decP[NACT * 96];         // [c][k] (transposed decW)

__global__ void setup_kernel(const float* __restrict__ Wih,
                             const float* __restrict__ Whh,
                             const float* __restrict__ qW,
                             const float* __restrict__ kW,
                             const float* __restrict__ vW,
                             const float* __restrict__ decW)
{
    const int stride = gridDim.x * blockDim.x;
    const int t0 = blockIdx.x * blockDim.x + threadIdx.x;
    for (int idx = t0; idx < HDIM * 192; idx += stride) {
        int k = idx / 192, j = idx - k * 192;
        g_WihT[idx] = Wih[j * HDIM + k];
        g_WhhT[idx] = Whh[j * HDIM + k];
    }
    for (int idx = t0; idx < HDIM * 96; idx += stride) {
        int k = idx / 96, a = idx - k * 96;
        float v;
        if (a < 32)      v = qW[k * 32 + a];
        else if (a < 64) v = kW[k * 32 + (a - 32)];
        else             v = vW[k * 32 + (a - 64)];
        g_qkvW[idx] = v;
    }
    for (int idx = t0; idx < NACT * 96; idx += stride) {
        int c = idx / 96, k = idx - c * 96;
        g_decP[idx] = decW[k * NACT + c];
    }
}

// ---------------- f32x2 helpers ----------------
__device__ __forceinline__ void ffma2(ull& acc, ull a, ull b) {
    asm("fma.rn.f32x2 %0, %1, %2, %0;" : "+l"(acc) : "l"(a), "l"(b));
}
__device__ __forceinline__ ull pack2(float x) {
    ull d; unsigned xi = __float_as_uint(x);
    asm("mov.b64 %0, {%1, %1};" : "=l"(d) : "r"(xi));
    return d;
}
__device__ __forceinline__ float2 unpack2(ull v) {
    float2 r;
    asm("mov.b64 {%0, %1}, %2;" : "=f"(r.x), "=f"(r.y) : "l"(v));
    return r;
}
__device__ __forceinline__ float hsum2(ull v) {
    float2 r = unpack2(v);
    return r.x + r.y;
}
__device__ __forceinline__ unsigned saddr(const void* p) {
    return (unsigned)__cvta_generic_to_shared(p);
}
__device__ __forceinline__ float tanh_fast(float x) {
    float r; asm("tanh.approx.f32 %0, %1;" : "=f"(r) : "f"(x)); return r;
}
__device__ __forceinline__ float sigmoid_fast(float s) {
    return fmaf(tanh_fast(0.5f * s), 0.5f, 0.5f);
}

// GRU gate pair: ax = x @ WihT[:, g64+c0..+3], ah = h @ WhhT[...]
// float4 activation loads (1 LDS.128 per row per 4k), packs from registers.
__device__ __forceinline__ void gate_pass(const float* __restrict__ x_s,
                                          const float* __restrict__ h_s,
                                          int g, int r0, int c0,
                                          ull ax[4][2], ull ah[4][2])
{
#pragma unroll
    for (int i = 0; i < 4; i++) { ax[i][0] = 0; ax[i][1] = 0; ah[i][0] = 0; ah[i][1] = 0; }
#pragma unroll 2
    for (int kk = 0; kk < HDIM; kk += 4) {
        float4 xv[4], hv[4];
#pragma unroll
        for (int i = 0; i < 4; i++) {
            xv[i] = *reinterpret_cast<const float4*>(&x_s[(r0 + i) * PT + kk]);
            hv[i] = *reinterpret_cast<const float4*>(&h_s[(r0 + i) * PT + kk]);
        }
#pragma unroll
        for (int q = 0; q < 4; q++) {
            const int k = kk + q;
            const ulonglong2 wx = *reinterpret_cast<const ulonglong2*>(&g_WihT[k * 192 + g * 64 + c0]);
            const ulonglong2 wh = *reinterpret_cast<const ulonglong2*>(&g_WhhT[k * 192 + g * 64 + c0]);
#pragma unroll
            for (int i = 0; i < 4; i++) {
                const float* xp = &xv[i].x;
                const float* hp = &hv[i].x;
                ull xd = pack2(xp[q]);
                ull hd = pack2(hp[q]);
                ffma2(ax[i][0], xd, wx.x); ffma2(ax[i][1], xd, wx.y);
                ffma2(ah[i][0], hd, wh.x); ffma2(ah[i][1], hd, wh.y);
            }
        }
    }
}

__global__ void __launch_bounds__(NTHREADS, 2)
fused_kernel(const float* __restrict__ obs,
             const float* __restrict__ hid,
             const float* __restrict__ encW,
             const float* __restrict__ encb,
             const float* __restrict__ bih,
             const float* __restrict__ bhh,
             const float* __restrict__ vb,
             const float* __restrict__ decb,
             float* __restrict__ outp,
             float* __restrict__ houtp)
{
    extern __shared__ float sm[];
    float* Abuf0 = sm;                 // [64][PT] obs tile (double buffer)
    float* Abuf1 = sm + 4352;
    float* x_s   = sm + 8704;          // [64][PT] encoder output
    float* h_s   = sm + 13056;         // [64][PT] hidden_state
    float* ho_s  = sm + 17408;         // [64][PH] h_out | xatt
    float* qkv_s = sm;                 // [64][PQ] overlays A buffers (dead)

    const int tid  = threadIdx.x;
    const int trow = tid >> 4;
    const int tcol = tid & 15;
    const int r0 = trow * 4;
    const int c0 = tcol * 4;
    const int rowbase = blockIdx.x * BM;

    // ---- prefetch obs tile 0 via cp.async ----
    {
#pragma unroll
        for (int c = 0; c < 4; c++) {
            int chunk = tid + c * 256;               // 1024 chunks of 16B
            int row = chunk >> 4, off = (chunk & 15) * 4;
            const float* src = obs + (size_t)(rowbase + row) * DIN + off;
            unsigned d = saddr(&Abuf0[row * PT + off]);
            asm volatile("cp.async.cg.shared.global [%0], [%1], 16;" :: "r"(d), "l"(src));
        }
        asm volatile("cp.async.commit_group;");
    }

    // ---- load hidden_state tile (row-major, float4) ----
    for (int v = tid; v < BM * 16; v += NTHREADS) {
        int r = v >> 4, cq = (v & 15) * 4;
        *reinterpret_cast<float4*>(&h_s[r * PT + cq]) =
            *reinterpret_cast<const float4*>(&hid[(size_t)(rowbase + r) * HDIM + cq]);
    }

    // ---------------- encoder: x = relu(obs @ enc_W + enc_b) ----------------
    {
        ull eacc[4][2];
#pragma unroll
        for (int i = 0; i < 4; i++) { eacc[i][0] = 0; eacc[i][1] = 0; }

#pragma unroll
        for (int kt = 0; kt < 4; kt++) {
            __syncthreads();
            if (kt < 3) {
                float* dst = ((kt + 1) & 1) ? Abuf1 : Abuf0;
#pragma unroll
                for (int c = 0; c < 4; c++) {
                    int chunk = tid + c * 256;
                    int row = chunk >> 4, off = (chunk & 15) * 4;
                    const float* src = obs + (size_t)(rowbase + row) * DIN + (kt + 1) * 64 + off;
                    unsigned d = saddr(&dst[row * PT + off]);
                    asm volatile("cp.async.cg.shared.global [%0], [%1], 16;" :: "r"(d), "l"(src));
                }
                asm volatile("cp.async.commit_group;");
                asm volatile("cp.async.wait_group 1;");
            } else {
                asm volatile("cp.async.wait_group 0;");
            }
            __syncthreads();

            const float* Ac = (kt & 1) ? Abuf1 : Abuf0;
#pragma unroll 2
            for (int kk = 0; kk < 64; kk += 4) {
                float4 xv[4];
#pragma unroll
                for (int i = 0; i < 4; i++)
                    xv[i] = *reinterpret_cast<const float4*>(&Ac[(r0 + i) * PT + kk]);
#pragma unroll
                for (int q = 0; q < 4; q++) {
                    const int k = kt * 64 + kk + q;
                    const ulonglong2 w = *reinterpret_cast<const ulonglong2*>(&encW[(size_t)k * HDIM + c0]);
#pragma unroll
                    for (int i = 0; i < 4; i++) {
                        const float* xp = &xv[i].x;
                        ull xd = pack2(xp[q]);
                        ffma2(eacc[i][0], xd, w.x);
                        ffma2(eacc[i][1], xd, w.y);
                    }
                }
            }
        }
        const float4 b4 = *reinterpret_cast<const float4*>(&encb[c0]);
#pragma unroll
        for (int i = 0; i < 4; i++) {
            float2 p0 = unpack2(eacc[i][0]), p1 = unpack2(eacc[i][1]);
            float4 o;
            o.x = fmaxf(p0.x + b4.x, 0.f); o.y = fmaxf(p0.y + b4.y, 0.f);
            o.z = fmaxf(p1.x + b4.z, 0.f); o.w = fmaxf(p1.y + b4.w, 0.f);
            *reinterpret_cast<float4*>(&x_s[(r0 + i) * PT + c0]) = o;
        }
    }
    __syncthreads();

    // ---------------- GRU cell (r, z kept in registers) ----------------
    {
        float rg[4][4], zg[4][4];
        ull ax[4][2], ah[4][2];

        gate_pass(x_s, h_s, 0, r0, c0, ax, ah);
        {
            const float4 bx = *reinterpret_cast<const float4*>(&bih[c0]);
            const float4 bh = *reinterpret_cast<const float4*>(&bhh[c0]);
            const float bs[4] = {bx.x + bh.x, bx.y + bh.y, bx.z + bh.z, bx.w + bh.w};
#pragma unroll
            for (int i = 0; i < 4; i++) {
                float2 px0 = unpack2(ax[i][0]), px1 = unpack2(ax[i][1]);
                float2 ph0 = unpack2(ah[i][0]), ph1 = unpack2(ah[i][1]);
                rg[i][0] = sigmoid_fast(px0.x + ph0.x + bs[0]);
                rg[i][1] = sigmoid_fast(px0.y + ph0.y + bs[1]);
                rg[i][2] = sigmoid_fast(px1.x + ph1.x + bs[2]);
                rg[i][3] = sigmoid_fast(px1.y + ph1.y + bs[3]);
            }
        }
        gate_pass(x_s, h_s, 1, r0, c0, ax, ah);
        {
            const float4 bx = *reinterpret_cast<const float4*>(&bih[64 + c0]);
            const float4 bh = *reinterpret_cast<const float4*>(&bhh[64 + c0]);
            const float bs[4] = {bx.x + bh.x, bx.y + bh.y, bx.z + bh.z, bx.w + bh.w};
#pragma unroll
            for (int i = 0; i < 4; i++) {
                float2 px0 = unpack2(ax[i][0]), px1 = unpack2(ax[i][1]);
                float2 ph0 = unpack2(ah[i][0]), ph1 = unpack2(ah[i][1]);
                zg[i][0] = sigmoid_fast(px0.x + ph0.x + bs[0]);
                zg[i][1] = sigmoid_fast(px0.y + ph0.y + bs[1]);
                zg[i][2] = sigmoid_fast(px1.x + ph1.x + bs[2]);
                zg[i][3] = sigmoid_fast(px1.y + ph1.y + bs[3]);
            }
        }
        gate_pass(x_s, h_s, 2, r0, c0, ax, ah);
        {
            const float4 bx = *reinterpret_cast<const float4*>(&bih[128 + c0]);
            const float4 bh = *reinterpret_cast<const float4*>(&bhh[128 + c0]);
            const float bxv[4] = {bx.x, bx.y, bx.z, bx.w}, bhv[4] = {bh.x, bh.y, bh.z, bh.w};
#pragma unroll
            for (int i = 0; i < 4; i++) {
                float2 px0 = unpack2(ax[i][0]), px1 = unpack2(ax[i][1]);
                float2 ph0 = unpack2(ah[i][0]), ph1 = unpack2(ah[i][1]);
                float xn[4] = {px0.x + bxv[0], px0.y + bxv[1], px1.x + bxv[2], px1.y + bxv[3]};
                float hn[4] = {ph0.x + bhv[0], ph0.y + bhv[1], ph1.x + bhv[2], ph1.y + bhv[3]};
                float4 o;
                float* op = &o.x;
#pragma unroll
                for (int j = 0; j < 4; j++) {
                    float nn = tanh_fast(xn[j] + rg[i][j] * hn[j]);
                    float hp = h_s[(r0 + i) * PT + c0 + j];
                    op[j] = (1.f - zg[i][j]) * nn + zg[i][j] * hp;
                }
                *reinterpret_cast<float4*>(&ho_s[(r0 + i) * PH + c0]) = o;
            }
        }
    }
    __syncthreads();

    // ---------------- q|k|v = h_out @ [qW|kW|vW]  (N=96, tile 4x6) ----------
    {
        const int cq = tcol * 6;
        ull qa[4][3];
#pragma unroll
        for (int i = 0; i < 4; i++) { qa[i][0] = 0; qa[i][1] = 0; qa[i][2] = 0; }
#pragma unroll 2
        for (int kk = 0; kk < HDIM; kk += 4) {
            float4 hv4[4];
#pragma unroll
            for (int i = 0; i < 4; i++)
                hv4[i] = *reinterpret_cast<const float4*>(&ho_s[(r0 + i) * PH + kk]);
#pragma unroll
            for (int q = 0; q < 4; q++) {
                const int k = kk + q;
                const ull* wp = reinterpret_cast<const ull*>(&g_qkvW[k * 96 + cq]);
                ull w0 = wp[0], w1 = wp[1], w2 = wp[2];
#pragma unroll
                for (int i = 0; i < 4; i++) {
                    const float* hp = &hv4[i].x;
                    ull hd = pack2(hp[q]);
                    ffma2(qa[i][0], hd, w0); ffma2(qa[i][1], hd, w1); ffma2(qa[i][2], hd, w2);
                }
            }
        }
#pragma unroll
        for (int i = 0; i < 4; i++) {
#pragma unroll
            for (int m = 0; m < 3; m++) {
                float2 p = unpack2(qa[i][m]);
                float pv[2] = {p.x, p.y};
#pragma unroll
                for (int l = 0; l < 2; l++) {
                    int cg = cq + 2 * m + l;
                    float v = pv[l];
                    if (cg >= 64) v = fmaxf(v + vb[cg - 64], 0.f);
                    qkv_s[(r0 + i) * PQ + cg] = v;
                }
            }
        }
        // h_out writeback (coalesced float4) — independent of attention
        for (int v = tid; v < BM * 16; v += NTHREADS) {
            int r = v >> 4, cc = (v & 15) * 4;
            *reinterpret_cast<float4*>(&houtp[(size_t)(rowbase + r) * HDIM + cc]) =
                *reinterpret_cast<const float4*>(&ho_s[r * PH + cc]);
        }
    }
    __syncthreads();

    // ---------------- exclude-self attention (8 groups of 8 rows) -----------
    if (tid < BM) {
        const int ii = tid & 7;
        const int base = tid & ~7;
        float q[ADIM];
#pragma unroll
        for (int a4 = 0; a4 < 8; a4++) {
            float4 t = *reinterpret_cast<const float4*>(&qkv_s[tid * PQ + a4 * 4]);
            q[a4 * 4 + 0] = t.x; q[a4 * 4 + 1] = t.y; q[a4 * 4 + 2] = t.z; q[a4 * 4 + 3] = t.w;
        }
        float sc[NS]; float mx = -1e30f;
#pragma unroll
        for (int j = 0; j < NS; j++) {
            float s = 0.f;
#pragma unroll
            for (int a4 = 0; a4 < 8; a4++) {
                float4 t = *reinterpret_cast<const float4*>(&qkv_s[(base + j) * PQ + 32 + a4 * 4]);
                s = fmaf(q[a4 * 4 + 0], t.x, s); s = fmaf(q[a4 * 4 + 1], t.y, s);
                s = fmaf(q[a4 * 4 + 2], t.z, s); s = fmaf(q[a4 * 4 + 3], t.w, s);
            }
            s *= 0.17677669529663689f;
            if (j == ii) s = -1e9f;
            sc[j] = s; mx = fmaxf(mx, s);
        }
        float sum = 0.f;
#pragma unroll
        for (int j = 0; j < NS; j++) { sc[j] = __expf(sc[j] - mx); sum += sc[j]; }
        const float inv = __fdividef(1.f, sum);
        float xa[ADIM];
#pragma unroll
        for (int a = 0; a < ADIM; a++) xa[a] = 0.f;
#pragma unroll
        for (int j = 0; j < NS; j++) {
            float w = sc[j] * inv;
#pragma unroll
            for (int a4 = 0; a4 < 8; a4++) {
                float4 t = *reinterpret_cast<const float4*>(&qkv_s[(base + j) * PQ + 64 + a4 * 4]);
                xa[a4 * 4 + 0] = fmaf(w, t.x, xa[a4 * 4 + 0]);
                xa[a4 * 4 + 1] = fmaf(w, t.y, xa[a4 * 4 + 1]);
                xa[a4 * 4 + 2] = fmaf(w, t.z, xa[a4 * 4 + 2]);
                xa[a4 * 4 + 3] = fmaf(w, t.w, xa[a4 * 4 + 3]);
            }
        }
#pragma unroll
        for (int a4 = 0; a4 < 8; a4++) {
            float4 o = make_float4(xa[a4 * 4], xa[a4 * 4 + 1], xa[a4 * 4 + 2], xa[a4 * 4 + 3]);
            *reinterpret_cast<float4*>(&ho_s[tid * PH + 64 + a4 * 4]) = o;
        }
    }
    __syncthreads();

    // ---------------- decoder: out = [h_out|xatt] @ decW + decb -------------
    for (int idx = tid; idx < BM * NACT; idx += NTHREADS) {
        int r = idx / NACT;
        int c = idx - r * NACT;
        const ull* hp = reinterpret_cast<const ull*>(&ho_s[r * PH]);
        const ull* wp = reinterpret_cast<const ull*>(&g_decP[c * 96]);
        ull acc = 0;
#pragma unroll 8
        for (int kp = 0; kp < 48; kp++) ffma2(acc, hp[kp], wp[kp]);
        outp[(size_t)(rowbase + r) * NACT + c] = hsum2(acc) + decb[c];
    }
}

extern "C" void kernel_launch(void* const* d_in, const int* in_sizes, int n_in,
                              void* d_out, int out_size)
{
    (void)in_sizes; (void)n_in; (void)out_size;
    const float* obs  = (const float*)d_in[0];
    const float* hid  = (const float*)d_in[1];
    const float* encW = (const float*)d_in[2];
    const float* encb = (const float*)d_in[3];
    const float* Wih  = (const float*)d_in[4];
    const float* Whh  = (const float*)d_in[5];
    const float* bih  = (const float*)d_in[6];
    const float* bhh  = (const float*)d_in[7];
    const float* qW   = (const float*)d_in[8];
    const float* kW   = (const float*)d_in[9];
    const float* vW   = (const float*)d_in[10];
    const float* vb   = (const float*)d_in[11];
    const float* decW = (const float*)d_in[12];
    const float* decb = (const float*)d_in[13];

    float* outp  = (float*)d_out;                 // [B, 14]
    float* houtp = outp + (size_t)BTOT * NACT;    // [B, 64]

    setup_kernel<<<64, 256>>>(Wih, Whh, qW, kW, vW, decW);

    const int smem_bytes = 23808 * sizeof(float); // 95,232 B
    cudaFuncSetAttribute(fused_kernel,
                         cudaFuncAttributeMaxDynamicSharedMemorySize, smem_bytes);
    fused_kernel<<<BTOT / BM, NTHREADS, smem_bytes>>>(
        obs, hid, encW, encb, bih, bhh, vb, decb, outp, houtp);
}

// round 5
// speedup vs baseline: 1.3832x; 1.1614x over previous
#include <cuda_runtime.h>
#include <math.h>

#define BTOT   65536
#define DIN    256
#define HDIM   64
#define ADIM   32
#define NACT   14
#define NS     8
#define BM     64
#define PT     68        // feature-major pitch: tile[feat][row], rows 0..63
#define NTHREADS 256

typedef unsigned long long ull;

// ---- persistent repacked weights ----
__device__ __align__(16) float g_WihT[HDIM * 3 * HDIM];   // [k=64][j=192]
__device__ __align__(16) float g_WhhT[HDIM * 3 * HDIM];   // [k=64][j=192]
__device__ __align__(16) float g_qkvW[HDIM * 96];         // [k=64][q|k|v=96]
__device__ __align__(16) float g_decP[NACT * 96];         // [c][k]  (decW^T)

__global__ void setup_kernel(const float* __restrict__ Wih,
                             const float* __restrict__ Whh,
                             const float* __restrict__ qW,
                             const float* __restrict__ kW,
                             const float* __restrict__ vW,
                             const float* __restrict__ decW)
{
    const int stride = gridDim.x * blockDim.x;
    const int t0 = blockIdx.x * blockDim.x + threadIdx.x;
    for (int idx = t0; idx < HDIM * 192; idx += stride) {
        int k = idx / 192, j = idx - k * 192;
        g_WihT[idx] = Wih[j * HDIM + k];
        g_WhhT[idx] = Whh[j * HDIM + k];
    }
    for (int idx = t0; idx < HDIM * 96; idx += stride) {
        int k = idx / 96, a = idx - k * 96;
        float v;
        if (a < 32)      v = qW[k * 32 + a];
        else if (a < 64) v = kW[k * 32 + (a - 32)];
        else             v = vW[k * 32 + (a - 64)];
        g_qkvW[idx] = v;
    }
    for (int idx = t0; idx < NACT * 96; idx += stride) {
        int c = idx / 96, k = idx - c * 96;
        g_decP[idx] = decW[k * NACT + c];
    }
}

// ---------------- f32x2 helpers ----------------
__device__ __forceinline__ void ffma2(ull& acc, ull a, ull b) {
    asm("fma.rn.f32x2 %0, %1, %2, %0;" : "+l"(acc) : "l"(a), "l"(b));
}
__device__ __forceinline__ ull pack2(float x) {
    ull d; unsigned xi = __float_as_uint(x);
    asm("mov.b64 %0, {%1, %1};" : "=l"(d) : "r"(xi));
    return d;
}
__device__ __forceinline__ ull pack_ab(float a, float b) {
    ull d;
    asm("mov.b64 %0, {%1, %2};" : "=l"(d) : "f"(a), "f"(b));
    return d;
}
__device__ __forceinline__ float2 unpack2(ull v) {
    float2 r;
    asm("mov.b64 {%0, %1}, %2;" : "=f"(r.x), "=f"(r.y) : "l"(v));
    return r;
}
__device__ __forceinline__ float hsum2(ull v) {
    float2 r = unpack2(v);
    return r.x + r.y;
}
__device__ __forceinline__ unsigned saddr(const void* p) {
    return (unsigned)__cvta_generic_to_shared(p);
}
__device__ __forceinline__ float tanh_fast(float x) {
    float r; asm("tanh.approx.f32 %0, %1;" : "=f"(r) : "f"(x)); return r;
}
__device__ __forceinline__ float sigmoid_fast(float s) {
    return fmaf(tanh_fast(0.5f * s), 0.5f, 0.5f);
}

__global__ void __launch_bounds__(NTHREADS, 2)
fused_kernel(const float* __restrict__ obs,
             const float* __restrict__ hid,
             const float* __restrict__ encW,
             const float* __restrict__ encb,
             const float* __restrict__ bih,
             const float* __restrict__ bhh,
             const float* __restrict__ vb,
             const float* __restrict__ decb,
             float* __restrict__ outp,
             float* __restrict__ houtp)
{
    extern __shared__ float sm[];
    float* Abuf0 = sm;                 // [64 rows][PT]  row-major obs tile (double buffer)
    float* Abuf1 = sm + 4352;
    float* x_s   = sm + 8704;          // [64 feat][PT]  encoder output (feat-major)
    float* h_s   = sm + 13056;         // [64 feat][PT]  hidden_state (feat-major)
    float* ho_s  = sm + 17408;         // [96 feat][PT]  h_out (0..63) | xatt (64..95)
    float* qkv_s = sm;                 // [96 feat][PT]  overlays Abufs (dead after encoder)

    const int tid  = threadIdx.x;
    const int trow = tid >> 4;
    const int tcol = tid & 15;
    const int r0 = trow * 4;
    const int c0 = tcol * 4;
    const int rowbase = blockIdx.x * BM;

    // ---- prefetch obs tile 0 via cp.async ----
    {
#pragma unroll
        for (int c = 0; c < 4; c++) {
            int chunk = tid + c * 256;
            int row = chunk >> 4, off = (chunk & 15) * 4;
            const float* src = obs + (size_t)(rowbase + row) * DIN + off;
            unsigned d = saddr(&Abuf0[row * PT + off]);
            asm volatile("cp.async.cg.shared.global [%0], [%1], 16;" :: "r"(d), "l"(src));
        }
        asm volatile("cp.async.commit_group;");
    }

    // ---- load hidden_state, transposed to feat-major h_s[k][r] ----
    for (int v = tid; v < BM * 16; v += NTHREADS) {
        int r = v >> 4, c4 = (v & 15) * 4;
        float4 t = *reinterpret_cast<const float4*>(&hid[(size_t)(rowbase + r) * HDIM + c4]);
        h_s[(c4 + 0) * PT + r] = t.x;
        h_s[(c4 + 1) * PT + r] = t.y;
        h_s[(c4 + 2) * PT + r] = t.z;
        h_s[(c4 + 3) * PT + r] = t.w;
    }

    // ---------------- encoder: x = relu(obs @ enc_W + enc_b) ----------------
    // R2-proven form: scalar activation broadcast, weight j-pairs.
    {
        ull eacc[4][2];
#pragma unroll
        for (int i = 0; i < 4; i++) { eacc[i][0] = 0; eacc[i][1] = 0; }

#pragma unroll
        for (int kt = 0; kt < 4; kt++) {
            __syncthreads();
            if (kt < 3) {
                float* dst = ((kt + 1) & 1) ? Abuf1 : Abuf0;
#pragma unroll
                for (int c = 0; c < 4; c++) {
                    int chunk = tid + c * 256;
                    int row = chunk >> 4, off = (chunk & 15) * 4;
                    const float* src = obs + (size_t)(rowbase + row) * DIN + (kt + 1) * 64 + off;
                    unsigned d = saddr(&dst[row * PT + off]);
                    asm volatile("cp.async.cg.shared.global [%0], [%1], 16;" :: "r"(d), "l"(src));
                }
                asm volatile("cp.async.commit_group;");
                asm volatile("cp.async.wait_group 1;");
            } else {
                asm volatile("cp.async.wait_group 0;");
            }
            __syncthreads();

            const float* Ac = (kt & 1) ? Abuf1 : Abuf0;
#pragma unroll 8
            for (int k = 0; k < 64; k++) {
                const ulonglong2 w = *reinterpret_cast<const ulonglong2*>(&encW[(size_t)(kt * 64 + k) * HDIM + c0]);
                ull xd[4];
#pragma unroll
                for (int i = 0; i < 4; i++) xd[i] = pack2(Ac[(r0 + i) * PT + k]);
#pragma unroll
                for (int i = 0; i < 4; i++) { ffma2(eacc[i][0], xd[i], w.x); ffma2(eacc[i][1], xd[i], w.y); }
            }
        }
        // epilogue: bias + relu, store feat-major as row-pairs (STS.64)
        const float4 b4 = *reinterpret_cast<const float4*>(&encb[c0]);
        const float bv[4] = {b4.x, b4.y, b4.z, b4.w};
        float xo[4][4];
#pragma unroll
        for (int i = 0; i < 4; i++) {
            float2 p0 = unpack2(eacc[i][0]), p1 = unpack2(eacc[i][1]);
            xo[i][0] = fmaxf(p0.x + bv[0], 0.f);
            xo[i][1] = fmaxf(p0.y + bv[1], 0.f);
            xo[i][2] = fmaxf(p1.x + bv[2], 0.f);
            xo[i][3] = fmaxf(p1.y + bv[3], 0.f);
        }
#pragma unroll
        for (int j = 0; j < 4; j++) {
            *reinterpret_cast<ull*>(&x_s[(c0 + j) * PT + r0])     = pack_ab(xo[0][j], xo[1][j]);
            *reinterpret_cast<ull*>(&x_s[(c0 + j) * PT + r0 + 2]) = pack_ab(xo[2][j], xo[3][j]);
        }
    }
    __syncthreads();

    // ---------------- GRU cell (row-pair packed, fused x+h accumulators) ----
    {
        ull rgp[2][4], zgp[2][4], rnp[2][4];

        // ---- r gate ----
        {
            ull acc[2][4] = {{0,0,0,0},{0,0,0,0}};
#pragma unroll 4
            for (int k = 0; k < HDIM; k++) {
                const ulonglong2 xv = *reinterpret_cast<const ulonglong2*>(&x_s[k * PT + r0]);
                const ulonglong2 hv = *reinterpret_cast<const ulonglong2*>(&h_s[k * PT + r0]);
                const float4 wx = *reinterpret_cast<const float4*>(&g_WihT[k * 192 + c0]);
                const float4 wh = *reinterpret_cast<const float4*>(&g_WhhT[k * 192 + c0]);
                const float wxv[4] = {wx.x, wx.y, wx.z, wx.w};
                const float whv[4] = {wh.x, wh.y, wh.z, wh.w};
#pragma unroll
                for (int j = 0; j < 4; j++) {
                    ull wxp = pack2(wxv[j]), whp = pack2(whv[j]);
                    ffma2(acc[0][j], xv.x, wxp); ffma2(acc[1][j], xv.y, wxp);
                    ffma2(acc[0][j], hv.x, whp); ffma2(acc[1][j], hv.y, whp);
                }
            }
            const float4 bx = *reinterpret_cast<const float4*>(&bih[c0]);
            const float4 bh = *reinterpret_cast<const float4*>(&bhh[c0]);
            const float bs[4] = {bx.x + bh.x, bx.y + bh.y, bx.z + bh.z, bx.w + bh.w};
#pragma unroll
            for (int p = 0; p < 2; p++)
#pragma unroll
                for (int j = 0; j < 4; j++) {
                    float2 v = unpack2(acc[p][j]);
                    rgp[p][j] = pack_ab(sigmoid_fast(v.x + bs[j]), sigmoid_fast(v.y + bs[j]));
                }
        }

        // ---- z gate ----
        {
            ull acc[2][4] = {{0,0,0,0},{0,0,0,0}};
#pragma unroll 4
            for (int k = 0; k < HDIM; k++) {
                const ulonglong2 xv = *reinterpret_cast<const ulonglong2*>(&x_s[k * PT + r0]);
                const ulonglong2 hv = *reinterpret_cast<const ulonglong2*>(&h_s[k * PT + r0]);
                const float4 wx = *reinterpret_cast<const float4*>(&g_WihT[k * 192 + 64 + c0]);
                const float4 wh = *reinterpret_cast<const float4*>(&g_WhhT[k * 192 + 64 + c0]);
                const float wxv[4] = {wx.x, wx.y, wx.z, wx.w};
                const float whv[4] = {wh.x, wh.y, wh.z, wh.w};
#pragma unroll
                for (int j = 0; j < 4; j++) {
                    ull wxp = pack2(wxv[j]), whp = pack2(whv[j]);
                    ffma2(acc[0][j], xv.x, wxp); ffma2(acc[1][j], xv.y, wxp);
                    ffma2(acc[0][j], hv.x, whp); ffma2(acc[1][j], hv.y, whp);
                }
            }
            const float4 bx = *reinterpret_cast<const float4*>(&bih[64 + c0]);
            const float4 bh = *reinterpret_cast<const float4*>(&bhh[64 + c0]);
            const float bs[4] = {bx.x + bh.x, bx.y + bh.y, bx.z + bh.z, bx.w + bh.w};
#pragma unroll
            for (int p = 0; p < 2; p++)
#pragma unroll
                for (int j = 0; j < 4; j++) {
                    float2 v = unpack2(acc[p][j]);
                    zgp[p][j] = pack_ab(sigmoid_fast(v.x + bs[j]), sigmoid_fast(v.y + bs[j]));
                }
        }

        // ---- n gate: hn pass ----
        {
            ull acc[2][4] = {{0,0,0,0},{0,0,0,0}};
#pragma unroll 4
            for (int k = 0; k < HDIM; k++) {
                const ulonglong2 hv = *reinterpret_cast<const ulonglong2*>(&h_s[k * PT + r0]);
                const float4 wh = *reinterpret_cast<const float4*>(&g_WhhT[k * 192 + 128 + c0]);
                const float whv[4] = {wh.x, wh.y, wh.z, wh.w};
#pragma unroll
                for (int j = 0; j < 4; j++) {
                    ull whp = pack2(whv[j]);
                    ffma2(acc[0][j], hv.x, whp); ffma2(acc[1][j], hv.y, whp);
                }
            }
            const float4 bh = *reinterpret_cast<const float4*>(&bhh[128 + c0]);
            const float bhv[4] = {bh.x, bh.y, bh.z, bh.w};
#pragma unroll
            for (int p = 0; p < 2; p++)
#pragma unroll
                for (int j = 0; j < 4; j++) {
                    float2 v = unpack2(acc[p][j]);
                    float2 r = unpack2(rgp[p][j]);
                    rnp[p][j] = pack_ab(r.x * (v.x + bhv[j]), r.y * (v.y + bhv[j]));
                }
        }

        // ---- n gate: xn pass + blend + store ----
        {
            ull acc[2][4] = {{0,0,0,0},{0,0,0,0}};
#pragma unroll 4
            for (int k = 0; k < HDIM; k++) {
                const ulonglong2 xv = *reinterpret_cast<const ulonglong2*>(&x_s[k * PT + r0]);
                const float4 wx = *reinterpret_cast<const float4*>(&g_WihT[k * 192 + 128 + c0]);
                const float wxv[4] = {wx.x, wx.y, wx.z, wx.w};
#pragma unroll
                for (int j = 0; j < 4; j++) {
                    ull wxp = pack2(wxv[j]);
                    ffma2(acc[0][j], xv.x, wxp); ffma2(acc[1][j], xv.y, wxp);
                }
            }
            const float4 bx = *reinterpret_cast<const float4*>(&bih[128 + c0]);
            const float bxv[4] = {bx.x, bx.y, bx.z, bx.w};
#pragma unroll
            for (int p = 0; p < 2; p++)
#pragma unroll
                for (int j = 0; j < 4; j++) {
                    float2 xn = unpack2(acc[p][j]);
                    float2 rn = unpack2(rnp[p][j]);
                    float2 z  = unpack2(zgp[p][j]);
                    ull hp2 = *reinterpret_cast<const ull*>(&h_s[(c0 + j) * PT + r0 + 2 * p]);
                    float2 hp = unpack2(hp2);
                    float n0 = tanh_fast(xn.x + bxv[j] + rn.x);
                    float n1 = tanh_fast(xn.y + bxv[j] + rn.y);
                    float o0 = (1.f - z.x) * n0 + z.x * hp.x;
                    float o1 = (1.f - z.y) * n1 + z.y * hp.y;
                    *reinterpret_cast<ull*>(&ho_s[(c0 + j) * PT + r0 + 2 * p]) = pack_ab(o0, o1);
                }
        }
    }
    __syncthreads();

    // ---------------- q|k|v GEMM (N=96, 2 row-pairs x 6 cols) + h_out WB ----
    {
        // h_out writeback (gather feat-major -> coalesced float4 global store)
        for (int v = tid; v < BM * 16; v += NTHREADS) {
            int r = v >> 4, c4 = (v & 15) * 4;
            float4 t;
            t.x = ho_s[(c4 + 0) * PT + r];
            t.y = ho_s[(c4 + 1) * PT + r];
            t.z = ho_s[(c4 + 2) * PT + r];
            t.w = ho_s[(c4 + 3) * PT + r];
            *reinterpret_cast<float4*>(&houtp[(size_t)(rowbase + r) * HDIM + c4]) = t;
        }

        const int cq = tcol * 6;
        ull acc[2][6];
#pragma unroll
        for (int p = 0; p < 2; p++)
#pragma unroll
            for (int m = 0; m < 6; m++) acc[p][m] = 0;

#pragma unroll 4
        for (int k = 0; k < HDIM; k++) {
            const ulonglong2 hv = *reinterpret_cast<const ulonglong2*>(&ho_s[k * PT + r0]);
            const float2 w01 = *reinterpret_cast<const float2*>(&g_qkvW[k * 96 + cq]);
            const float2 w23 = *reinterpret_cast<const float2*>(&g_qkvW[k * 96 + cq + 2]);
            const float2 w45 = *reinterpret_cast<const float2*>(&g_qkvW[k * 96 + cq + 4]);
            const float wv[6] = {w01.x, w01.y, w23.x, w23.y, w45.x, w45.y};
#pragma unroll
            for (int m = 0; m < 6; m++) {
                ull wp = pack2(wv[m]);
                ffma2(acc[0][m], hv.x, wp);
                ffma2(acc[1][m], hv.y, wp);
            }
        }
#pragma unroll
        for (int p = 0; p < 2; p++)
#pragma unroll
            for (int m = 0; m < 6; m++) {
                int cg = cq + m;
                float2 v = unpack2(acc[p][m]);
                if (cg >= 64) {
                    float b = vb[cg - 64];
                    v.x = fmaxf(v.x + b, 0.f);
                    v.y = fmaxf(v.y + b, 0.f);
                }
                *reinterpret_cast<ull*>(&qkv_s[cg * PT + r0 + 2 * p]) = pack_ab(v.x, v.y);
            }
    }
    __syncthreads();

    // ---------------- exclude-self attention (packed over j-pairs) ----------
    if (tid < BM) {
        const int ii = tid & 7;
        const int base = tid & ~7;
        ull sp[4] = {0, 0, 0, 0};
#pragma unroll 8
        for (int a = 0; a < ADIM; a++) {
            ull qa = pack2(qkv_s[a * PT + tid]);
            const ulonglong2 k01 = *reinterpret_cast<const ulonglong2*>(&qkv_s[(32 + a) * PT + base]);
            const ulonglong2 k23 = *reinterpret_cast<const ulonglong2*>(&qkv_s[(32 + a) * PT + base + 4]);
            ffma2(sp[0], k01.x, qa); ffma2(sp[1], k01.y, qa);
            ffma2(sp[2], k23.x, qa); ffma2(sp[3], k23.y, qa);
        }
        float sc[NS];
#pragma unroll
        for (int jp = 0; jp < 4; jp++) {
            float2 v = unpack2(sp[jp]);
            sc[2 * jp]     = v.x * 0.17677669529663689f;
            sc[2 * jp + 1] = v.y * 0.17677669529663689f;
        }
        sc[ii] = -1e9f;
        float mx = -1e30f;
#pragma unroll
        for (int j = 0; j < NS; j++) mx = fmaxf(mx, sc[j]);
        float sum = 0.f;
#pragma unroll
        for (int j = 0; j < NS; j++) { sc[j] = __expf(sc[j] - mx); sum += sc[j]; }
        const float inv = __fdividef(1.f, sum);
        ull wp[4];
#pragma unroll
        for (int jp = 0; jp < 4; jp++)
            wp[jp] = pack_ab(sc[2 * jp] * inv, sc[2 * jp + 1] * inv);
#pragma unroll 8
        for (int a = 0; a < ADIM; a++) {
            const ulonglong2 v01 = *reinterpret_cast<const ulonglong2*>(&qkv_s[(64 + a) * PT + base]);
            const ulonglong2 v23 = *reinterpret_cast<const ulonglong2*>(&qkv_s[(64 + a) * PT + base + 4]);
            ull t = 0;
            ffma2(t, v01.x, wp[0]); ffma2(t, v01.y, wp[1]);
            ffma2(t, v23.x, wp[2]); ffma2(t, v23.y, wp[3]);
            ho_s[(64 + a) * PT + tid] = hsum2(t);
        }
    }
    __syncthreads();

    // ---------------- decoder: out = [h_out|xatt] @ decW + decb -------------
    // row-pair packed: item = (row-pair pr, col c); 32*14 = 448 items
    for (int it = tid; it < 448; it += NTHREADS) {
        int pr = it & 31, c = it >> 5;
        ull acc = 0;
#pragma unroll 6
        for (int k4 = 0; k4 < 24; k4++) {
            const float4 wv = *reinterpret_cast<const float4*>(&g_decP[c * 96 + k4 * 4]);
            ull h0 = *reinterpret_cast<const ull*>(&ho_s[(k4 * 4 + 0) * PT + 2 * pr]);
            ull h1 = *reinterpret_cast<const ull*>(&ho_s[(k4 * 4 + 1) * PT + 2 * pr]);
            ull h2 = *reinterpret_cast<const ull*>(&ho_s[(k4 * 4 + 2) * PT + 2 * pr]);
            ull h3 = *reinterpret_cast<const ull*>(&ho_s[(k4 * 4 + 3) * PT + 2 * pr]);
            ffma2(acc, h0, pack2(wv.x));
            ffma2(acc, h1, pack2(wv.y));
            ffma2(acc, h2, pack2(wv.z));
            ffma2(acc, h3, pack2(wv.w));
        }
        float2 p = unpack2(acc);
        float b = decb[c];
        size_t r = (size_t)(rowbase + 2 * pr);
        outp[r * NACT + c]       = p.x + b;
        outp[(r + 1) * NACT + c] = p.y + b;
    }
}

extern "C" void kernel_launch(void* const* d_in, const int* in_sizes, int n_in,
                              void* d_out, int out_size)
{
    (void)in_sizes; (void)n_in; (void)out_size;
    const float* obs  = (const float*)d_in[0];
    const float* hid  = (const float*)d_in[1];
    const float* encW = (const float*)d_in[2];
    const float* encb = (const float*)d_in[3];
    const float* Wih  = (const float*)d_in[4];
    const float* Whh  = (const float*)d_in[5];
    const float* bih  = (const float*)d_in[6];
    const float* bhh  = (const float*)d_in[7];
    const float* qW   = (const float*)d_in[8];
    const float* kW   = (const float*)d_in[9];
    const float* vW   = (const float*)d_in[10];
    const float* vb   = (const float*)d_in[11];
    const float* decW = (const float*)d_in[12];
    const float* decb = (const float*)d_in[13];

    float* outp  = (float*)d_out;                 // [B, 14]
    float* houtp = outp + (size_t)BTOT * NACT;    // [B, 64]

    setup_kernel<<<64, 256>>>(Wih, Whh, qW, kW, vW, decW);

    const int smem_bytes = (17408 + 96 * PT) * sizeof(float); // 95,744 B
    cudaFuncSetAttribute(fused_kernel,
                         cudaFuncAttributeMaxDynamicSharedMemorySize, smem_bytes);
    fused_kernel<<<BTOT / BM, NTHREADS, smem_bytes>>>(
        obs, hid, encW, encb, bih, bhh, vb, decb, outp, houtp);
}

// round 6
// speedup vs baseline: 1.4122x; 1.0210x over previous
#include <cuda_runtime.h>
#include <math.h>

#define BTOT   65536
#define DIN    256
#define HDIM   64
#define ADIM   32
#define NACT   14
#define NS     8
#define BM     64
#define PT     68        // feature-major pitch: tile[feat][row], rows 0..63
#define NTHREADS 256

typedef unsigned long long ull;

// ---- persistent repacked weights ----
__device__ __align__(16) float g_WihT[HDIM * 3 * HDIM];   // [k=64][j=192]
__device__ __align__(16) float g_WhhT[HDIM * 3 * HDIM];   // [k=64][j=192]
__device__ __align__(16) float g_qkvW[HDIM * 96];         // [k=64][q|k|v=96]
__device__ __align__(16) float g_decP[NACT * 96];         // [c][k]  (decW^T)

__global__ void setup_kernel(const float* __restrict__ Wih,
                             const float* __restrict__ Whh,
                             const float* __restrict__ qW,
                             const float* __restrict__ kW,
                             const float* __restrict__ vW,
                             const float* __restrict__ decW)
{
    const int stride = gridDim.x * blockDim.x;
    const int t0 = blockIdx.x * blockDim.x + threadIdx.x;
    for (int idx = t0; idx < HDIM * 192; idx += stride) {
        int k = idx / 192, j = idx - k * 192;
        g_WihT[idx] = Wih[j * HDIM + k];
        g_WhhT[idx] = Whh[j * HDIM + k];
    }
    for (int idx = t0; idx < HDIM * 96; idx += stride) {
        int k = idx / 96, a = idx - k * 96;
        float v;
        if (a < 32)      v = qW[k * 32 + a];
        else if (a < 64) v = kW[k * 32 + (a - 32)];
        else             v = vW[k * 32 + (a - 64)];
        g_qkvW[idx] = v;
    }
    for (int idx = t0; idx < NACT * 96; idx += stride) {
        int c = idx / 96, k = idx - c * 96;
        g_decP[idx] = decW[k * NACT + c];
    }
}

// ---------------- f32x2 helpers ----------------
__device__ __forceinline__ void ffma2(ull& acc, ull a, ull b) {
    asm("fma.rn.f32x2 %0, %1, %2, %0;" : "+l"(acc) : "l"(a), "l"(b));
}
__device__ __forceinline__ ull pack2(float x) {
    ull d; unsigned xi = __float_as_uint(x);
    asm("mov.b64 %0, {%1, %1};" : "=l"(d) : "r"(xi));
    return d;
}
__device__ __forceinline__ ull pack_ab(float a, float b) {
    ull d;
    asm("mov.b64 %0, {%1, %2};" : "=l"(d) : "f"(a), "f"(b));
    return d;
}
__device__ __forceinline__ float2 unpack2(ull v) {
    float2 r;
    asm("mov.b64 {%0, %1}, %2;" : "=f"(r.x), "=f"(r.y) : "l"(v));
    return r;
}
__device__ __forceinline__ float hsum2(ull v) {
    float2 r = unpack2(v);
    return r.x + r.y;
}
__device__ __forceinline__ unsigned saddr(const void* p) {
    return (unsigned)__cvta_generic_to_shared(p);
}
__device__ __forceinline__ float tanh_fast(float x) {
    float r; asm("tanh.approx.f32 %0, %1;" : "=f"(r) : "f"(x)); return r;
}
__device__ __forceinline__ float sigmoid_fast(float s) {
    return fmaf(tanh_fast(0.5f * s), 0.5f, 0.5f);
}

__global__ void __launch_bounds__(NTHREADS, 3)
fused_kernel(const float* __restrict__ obs,
             const float* __restrict__ hid,
             const float* __restrict__ encW,
             const float* __restrict__ encb,
             const float* __restrict__ bih,
             const float* __restrict__ bhh,
             const float* __restrict__ vb,
             const float* __restrict__ decb,
             float* __restrict__ outp,
             float* __restrict__ houtp)
{
    extern __shared__ float sm[];
    // regionA [0, 8704): obs double buffer -> later ho_s (96*PT = 6528)
    float* Abuf0 = sm;
    float* Abuf1 = sm + 4352;
    float* ho_s  = sm;                 // [96 feat][PT]  h_out (0..63) | xatt (64..95)
    // regionB [8704, 17408): x_s + h_s -> later qkv_s (96*PT = 6528)
    float* x_s   = sm + 8704;          // [64 feat][PT]
    float* h_s   = sm + 13056;         // [64 feat][PT]
    float* qkv_s = sm + 8704;          // [96 feat][PT]

    const int tid  = threadIdx.x;
    const int trow = tid >> 4;
    const int tcol = tid & 15;
    const int r0 = trow * 4;
    const int c0 = tcol * 4;
    const int rowbase = blockIdx.x * BM;

    // ---- prefetch obs tile 0 via cp.async ----
    {
#pragma unroll
        for (int c = 0; c < 4; c++) {
            int chunk = tid + c * 256;
            int row = chunk >> 4, off = (chunk & 15) * 4;
            const float* src = obs + (size_t)(rowbase + row) * DIN + off;
            unsigned d = saddr(&Abuf0[row * PT + off]);
            asm volatile("cp.async.cg.shared.global [%0], [%1], 16;" :: "r"(d), "l"(src));
        }
        asm volatile("cp.async.commit_group;");
    }

    // ---- load hidden_state, transposed to feat-major h_s[k][r] ----
    for (int v = tid; v < BM * 16; v += NTHREADS) {
        int r = v >> 4, c4 = (v & 15) * 4;
        float4 t = *reinterpret_cast<const float4*>(&hid[(size_t)(rowbase + r) * HDIM + c4]);
        h_s[(c4 + 0) * PT + r] = t.x;
        h_s[(c4 + 1) * PT + r] = t.y;
        h_s[(c4 + 2) * PT + r] = t.z;
        h_s[(c4 + 3) * PT + r] = t.w;
    }

    // ---------------- encoder: x = relu(obs @ enc_W + enc_b) ----------------
    {
        ull eacc[4][2];
#pragma unroll
        for (int i = 0; i < 4; i++) { eacc[i][0] = 0; eacc[i][1] = 0; }

#pragma unroll
        for (int kt = 0; kt < 4; kt++) {
            __syncthreads();
            if (kt < 3) {
                float* dst = ((kt + 1) & 1) ? Abuf1 : Abuf0;
#pragma unroll
                for (int c = 0; c < 4; c++) {
                    int chunk = tid + c * 256;
                    int row = chunk >> 4, off = (chunk & 15) * 4;
                    const float* src = obs + (size_t)(rowbase + row) * DIN + (kt + 1) * 64 + off;
                    unsigned d = saddr(&dst[row * PT + off]);
                    asm volatile("cp.async.cg.shared.global [%0], [%1], 16;" :: "r"(d), "l"(src));
                }
                asm volatile("cp.async.commit_group;");
                asm volatile("cp.async.wait_group 1;");
            } else {
                asm volatile("cp.async.wait_group 0;");
            }
            __syncthreads();

            const float* Ac = (kt & 1) ? Abuf1 : Abuf0;
#pragma unroll 8
            for (int k = 0; k < 64; k++) {
                const ulonglong2 w = *reinterpret_cast<const ulonglong2*>(&encW[(size_t)(kt * 64 + k) * HDIM + c0]);
                ull xd[4];
#pragma unroll
                for (int i = 0; i < 4; i++) xd[i] = pack2(Ac[(r0 + i) * PT + k]);
#pragma unroll
                for (int i = 0; i < 4; i++) { ffma2(eacc[i][0], xd[i], w.x); ffma2(eacc[i][1], xd[i], w.y); }
            }
        }
        __syncthreads();   // all reads of Abuf done before x_s write? (x_s is regionB, fine)
        // epilogue: bias + relu, store feat-major as row-pairs (STS.64)
        const float4 b4 = *reinterpret_cast<const float4*>(&encb[c0]);
        const float bv[4] = {b4.x, b4.y, b4.z, b4.w};
#pragma unroll
        for (int i = 0; i < 4; i += 2) {
            float2 p0 = unpack2(eacc[i][0]), p1 = unpack2(eacc[i][1]);
            float2 q0 = unpack2(eacc[i + 1][0]), q1 = unpack2(eacc[i + 1][1]);
            float a0 = fmaxf(p0.x + bv[0], 0.f), a1 = fmaxf(p0.y + bv[1], 0.f);
            float a2 = fmaxf(p1.x + bv[2], 0.f), a3 = fmaxf(p1.y + bv[3], 0.f);
            float b0 = fmaxf(q0.x + bv[0], 0.f), b1 = fmaxf(q0.y + bv[1], 0.f);
            float b2 = fmaxf(q1.x + bv[2], 0.f), b3 = fmaxf(q1.y + bv[3], 0.f);
            *reinterpret_cast<ull*>(&x_s[(c0 + 0) * PT + r0 + i]) = pack_ab(a0, b0);
            *reinterpret_cast<ull*>(&x_s[(c0 + 1) * PT + r0 + i]) = pack_ab(a1, b1);
            *reinterpret_cast<ull*>(&x_s[(c0 + 2) * PT + r0 + i]) = pack_ab(a2, b2);
            *reinterpret_cast<ull*>(&x_s[(c0 + 3) * PT + r0 + i]) = pack_ab(a3, b3);
        }
    }
    __syncthreads();

    // ---------------- GRU cell: r -> rn -> n -> z+blend (min live regs) ----
    {
        ull carry[2][4];   // rg -> rn -> n

        // ---- r gate (fused x+h) ----
        {
            ull acc[2][4] = {{0,0,0,0},{0,0,0,0}};
#pragma unroll 4
            for (int k = 0; k < HDIM; k++) {
                const ulonglong2 xv = *reinterpret_cast<const ulonglong2*>(&x_s[k * PT + r0]);
                const ulonglong2 hv = *reinterpret_cast<const ulonglong2*>(&h_s[k * PT + r0]);
                const float4 wx = *reinterpret_cast<const float4*>(&g_WihT[k * 192 + c0]);
                const float4 wh = *reinterpret_cast<const float4*>(&g_WhhT[k * 192 + c0]);
                const float wxv[4] = {wx.x, wx.y, wx.z, wx.w};
                const float whv[4] = {wh.x, wh.y, wh.z, wh.w};
#pragma unroll
                for (int j = 0; j < 4; j++) {
                    ull wxp = pack2(wxv[j]), whp = pack2(whv[j]);
                    ffma2(acc[0][j], xv.x, wxp); ffma2(acc[1][j], xv.y, wxp);
                    ffma2(acc[0][j], hv.x, whp); ffma2(acc[1][j], hv.y, whp);
                }
            }
            const float4 bx = *reinterpret_cast<const float4*>(&bih[c0]);
            const float4 bh = *reinterpret_cast<const float4*>(&bhh[c0]);
            const float bs[4] = {bx.x + bh.x, bx.y + bh.y, bx.z + bh.z, bx.w + bh.w};
#pragma unroll
            for (int p = 0; p < 2; p++)
#pragma unroll
                for (int j = 0; j < 4; j++) {
                    float2 v = unpack2(acc[p][j]);
                    carry[p][j] = pack_ab(sigmoid_fast(v.x + bs[j]), sigmoid_fast(v.y + bs[j]));
                }
        }

        // ---- hn pass: carry = rg * (h@Whh_n + bhh_n) ----
        {
            ull acc[2][4] = {{0,0,0,0},{0,0,0,0}};
#pragma unroll 4
            for (int k = 0; k < HDIM; k++) {
                const ulonglong2 hv = *reinterpret_cast<const ulonglong2*>(&h_s[k * PT + r0]);
                const float4 wh = *reinterpret_cast<const float4*>(&g_WhhT[k * 192 + 128 + c0]);
                const float whv[4] = {wh.x, wh.y, wh.z, wh.w};
#pragma unroll
                for (int j = 0; j < 4; j++) {
                    ull whp = pack2(whv[j]);
                    ffma2(acc[0][j], hv.x, whp); ffma2(acc[1][j], hv.y, whp);
                }
            }
            const float4 bh = *reinterpret_cast<const float4*>(&bhh[128 + c0]);
            const float bhv[4] = {bh.x, bh.y, bh.z, bh.w};
#pragma unroll
            for (int p = 0; p < 2; p++)
#pragma unroll
                for (int j = 0; j < 4; j++) {
                    float2 v = unpack2(acc[p][j]);
                    float2 r = unpack2(carry[p][j]);
                    carry[p][j] = pack_ab(r.x * (v.x + bhv[j]), r.y * (v.y + bhv[j]));
                }
        }

        // ---- xn pass: carry = tanh(x@Wih_n + bih_n + carry) ----
        {
            ull acc[2][4] = {{0,0,0,0},{0,0,0,0}};
#pragma unroll 4
            for (int k = 0; k < HDIM; k++) {
                const ulonglong2 xv = *reinterpret_cast<const ulonglong2*>(&x_s[k * PT + r0]);
                const float4 wx = *reinterpret_cast<const float4*>(&g_WihT[k * 192 + 128 + c0]);
                const float wxv[4] = {wx.x, wx.y, wx.z, wx.w};
#pragma unroll
                for (int j = 0; j < 4; j++) {
                    ull wxp = pack2(wxv[j]);
                    ffma2(acc[0][j], xv.x, wxp); ffma2(acc[1][j], xv.y, wxp);
                }
            }
            const float4 bx = *reinterpret_cast<const float4*>(&bih[128 + c0]);
            const float bxv[4] = {bx.x, bx.y, bx.z, bx.w};
#pragma unroll
            for (int p = 0; p < 2; p++)
#pragma unroll
                for (int j = 0; j < 4; j++) {
                    float2 xn = unpack2(acc[p][j]);
                    float2 rn = unpack2(carry[p][j]);
                    carry[p][j] = pack_ab(tanh_fast(xn.x + bxv[j] + rn.x),
                                          tanh_fast(xn.y + bxv[j] + rn.y));
                }
        }

        // ---- z gate (fused x+h) + blend + store ho_s ----
        {
            ull acc[2][4] = {{0,0,0,0},{0,0,0,0}};
#pragma unroll 4
            for (int k = 0; k < HDIM; k++) {
                const ulonglong2 xv = *reinterpret_cast<const ulonglong2*>(&x_s[k * PT + r0]);
                const ulonglong2 hv = *reinterpret_cast<const ulonglong2*>(&h_s[k * PT + r0]);
                const float4 wx = *reinterpret_cast<const float4*>(&g_WihT[k * 192 + 64 + c0]);
                const float4 wh = *reinterpret_cast<const float4*>(&g_WhhT[k * 192 + 64 + c0]);
                const float wxv[4] = {wx.x, wx.y, wx.z, wx.w};
                const float whv[4] = {wh.x, wh.y, wh.z, wh.w};
#pragma unroll
                for (int j = 0; j < 4; j++) {
                    ull wxp = pack2(wxv[j]), whp = pack2(whv[j]);
                    ffma2(acc[0][j], xv.x, wxp); ffma2(acc[1][j], xv.y, wxp);
                    ffma2(acc[0][j], hv.x, whp); ffma2(acc[1][j], hv.y, whp);
                }
            }
            const float4 bx = *reinterpret_cast<const float4*>(&bih[64 + c0]);
            const float4 bh = *reinterpret_cast<const float4*>(&bhh[64 + c0]);
            const float bs[4] = {bx.x + bh.x, bx.y + bh.y, bx.z + bh.z, bx.w + bh.w};
            __syncthreads();   // regionA: obs buffers fully dead; ho_s writes begin
#pragma unroll
            for (int p = 0; p < 2; p++)
#pragma unroll
                for (int j = 0; j < 4; j++) {
                    float2 v = unpack2(acc[p][j]);
                    float2 n = unpack2(carry[p][j]);
                    ull hp2 = *reinterpret_cast<const ull*>(&h_s[(c0 + j) * PT + r0 + 2 * p]);
                    float2 hp = unpack2(hp2);
                    float z0 = sigmoid_fast(v.x + bs[j]);
                    float z1 = sigmoid_fast(v.y + bs[j]);
                    float o0 = (1.f - z0) * n.x + z0 * hp.x;
                    float o1 = (1.f - z1) * n.y + z1 * hp.y;
                    *reinterpret_cast<ull*>(&ho_s[(c0 + j) * PT + r0 + 2 * p]) = pack_ab(o0, o1);
                }
        }
    }
    __syncthreads();

    // ---------------- q|k|v GEMM (N=96) + h_out writeback -------------------
    {
        // h_out writeback (gather feat-major -> coalesced float4 global store)
        for (int v = tid; v < BM * 16; v += NTHREADS) {
            int r = v >> 4, c4 = (v & 15) * 4;
            float4 t;
            t.x = ho_s[(c4 + 0) * PT + r];
            t.y = ho_s[(c4 + 1) * PT + r];
            t.z = ho_s[(c4 + 2) * PT + r];
            t.w = ho_s[(c4 + 3) * PT + r];
            *reinterpret_cast<float4*>(&houtp[(size_t)(rowbase + r) * HDIM + c4]) = t;
        }

        const int cq = tcol * 6;
        ull acc[2][6];
#pragma unroll
        for (int p = 0; p < 2; p++)
#pragma unroll
            for (int m = 0; m < 6; m++) acc[p][m] = 0;

#pragma unroll 4
        for (int k = 0; k < HDIM; k++) {
            const ulonglong2 hv = *reinterpret_cast<const ulonglong2*>(&ho_s[k * PT + r0]);
            const float2 w01 = *reinterpret_cast<const float2*>(&g_qkvW[k * 96 + cq]);
            const float2 w23 = *reinterpret_cast<const float2*>(&g_qkvW[k * 96 + cq + 2]);
            const float2 w45 = *reinterpret_cast<const float2*>(&g_qkvW[k * 96 + cq + 4]);
            const float wv[6] = {w01.x, w01.y, w23.x, w23.y, w45.x, w45.y};
#pragma unroll
            for (int m = 0; m < 6; m++) {
                ull wp = pack2(wv[m]);
                ffma2(acc[0][m], hv.x, wp);
                ffma2(acc[1][m], hv.y, wp);
            }
        }
        __syncthreads();   // regionB: x_s/h_s dead; qkv_s writes begin
#pragma unroll
        for (int p = 0; p < 2; p++)
#pragma unroll
            for (int m = 0; m < 6; m++) {
                int cg = cq + m;
                float2 v = unpack2(acc[p][m]);
                if (cg >= 64) {
                    float b = vb[cg - 64];
                    v.x = fmaxf(v.x + b, 0.f);
                    v.y = fmaxf(v.y + b, 0.f);
                }
                *reinterpret_cast<ull*>(&qkv_s[cg * PT + r0 + 2 * p]) = pack_ab(v.x, v.y);
            }
    }
    __syncthreads();

    // ---------------- exclude-self attention (packed over j-pairs) ----------
    if (tid < BM) {
        const int ii = tid & 7;
        const int base = tid & ~7;
        ull sp[4] = {0, 0, 0, 0};
#pragma unroll 8
        for (int a = 0; a < ADIM; a++) {
            ull qa = pack2(qkv_s[a * PT + tid]);
            const ulonglong2 k01 = *reinterpret_cast<const ulonglong2*>(&qkv_s[(32 + a) * PT + base]);
            const ulonglong2 k23 = *reinterpret_cast<const ulonglong2*>(&qkv_s[(32 + a) * PT + base + 4]);
            ffma2(sp[0], k01.x, qa); ffma2(sp[1], k01.y, qa);
            ffma2(sp[2], k23.x, qa); ffma2(sp[3], k23.y, qa);
        }
        float sc[NS];
#pragma unroll
        for (int jp = 0; jp < 4; jp++) {
            float2 v = unpack2(sp[jp]);
            sc[2 * jp]     = v.x * 0.17677669529663689f;
            sc[2 * jp + 1] = v.y * 0.17677669529663689f;
        }
        sc[ii] = -1e9f;
        float mx = -1e30f;
#pragma unroll
        for (int j = 0; j < NS; j++) mx = fmaxf(mx, sc[j]);
        float sum = 0.f;
#pragma unroll
        for (int j = 0; j < NS; j++) { sc[j] = __expf(sc[j] - mx); sum += sc[j]; }
        const float inv = __fdividef(1.f, sum);
        ull wp[4];
#pragma unroll
        for (int jp = 0; jp < 4; jp++)
            wp[jp] = pack_ab(sc[2 * jp] * inv, sc[2 * jp + 1] * inv);
#pragma unroll 8
        for (int a = 0; a < ADIM; a++) {
            const ulonglong2 v01 = *reinterpret_cast<const ulonglong2*>(&qkv_s[(64 + a) * PT + base]);
            const ulonglong2 v23 = *reinterpret_cast<const ulonglong2*>(&qkv_s[(64 + a) * PT + base + 4]);
            ull t = 0;
            ffma2(t, v01.x, wp[0]); ffma2(t, v01.y, wp[1]);
            ffma2(t, v23.x, wp[2]); ffma2(t, v23.y, wp[3]);
            ho_s[(64 + a) * PT + tid] = hsum2(t);
        }
    }
    __syncthreads();

    // ---------------- decoder: out = [h_out|xatt] @ decW + decb -------------
    for (int it = tid; it < 448; it += NTHREADS) {
        int pr = it & 31, c = it >> 5;
        ull acc = 0;
#pragma unroll 6
        for (int k4 = 0; k4 < 24; k4++) {
            const float4 wv = *reinterpret_cast<const float4*>(&g_decP[c * 96 + k4 * 4]);
            ull h0 = *reinterpret_cast<const ull*>(&ho_s[(k4 * 4 + 0) * PT + 2 * pr]);
            ull h1 = *reinterpret_cast<const ull*>(&ho_s[(k4 * 4 + 1) * PT + 2 * pr]);
            ull h2 = *reinterpret_cast<const ull*>(&ho_s[(k4 * 4 + 2) * PT + 2 * pr]);
            ull h3 = *reinterpret_cast<const ull*>(&ho_s[(k4 * 4 + 3) * PT + 2 * pr]);
            ffma2(acc, h0, pack2(wv.x));
            ffma2(acc, h1, pack2(wv.y));
            ffma2(acc, h2, pack2(wv.z));
            ffma2(acc, h3, pack2(wv.w));
        }
        float2 p = unpack2(acc);
        float b = decb[c];
        size_t r = (size_t)(rowbase + 2 * pr);
        outp[r * NACT + c]       = p.x + b;
        outp[(r + 1) * NACT + c] = p.y + b;
    }
}

extern "C" void kernel_launch(void* const* d_in, const int* in_sizes, int n_in,
                              void* d_out, int out_size)
{
    (void)in_sizes; (void)n_in; (void)out_size;
    const float* obs  = (const float*)d_in[0];
    const float* hid  = (const float*)d_in[1];
    const float* encW = (const float*)d_in[2];
    const float* encb = (const float*)d_in[3];
    const float* Wih  = (const float*)d_in[4];
    const float* Whh  = (const float*)d_in[5];
    const float* bih  = (const float*)d_in[6];
    const float* bhh  = (const float*)d_in[7];
    const float* qW   = (const float*)d_in[8];
    const float* kW   = (const float*)d_in[9];
    const float* vW   = (const float*)d_in[10];
    const float* vb   = (const float*)d_in[11];
    const float* decW = (const float*)d_in[12];
    const float* decb = (const float*)d_in[13];

    float* outp  = (float*)d_out;                 // [B, 14]
    float* houtp = outp + (size_t)BTOT * NACT;    // [B, 64]

    setup_kernel<<<64, 256>>>(Wih, Whh, qW, kW, vW, decW);

    const int smem_bytes = 17408 * sizeof(float); // 69,632 B -> 3 CTAs/SM
    cudaFuncSetAttribute(fused_kernel,
                         cudaFuncAttributeMaxDynamicSharedMemorySize, smem_bytes);
    fused_kernel<<<BTOT / BM, NTHREADS, smem_bytes>>>(
        obs, hid, encW, encb, bih, bhh, vb, decb, outp, houtp);
}

// round 7
// speedup vs baseline: 1.6939x; 1.1994x over previous
#include <cuda_runtime.h>
#include <math.h>

#define BTOT   65536
#define DIN    256
#define HDIM   64
#define ADIM   32
#define NACT   14
#define NS     8
#define BM     64
#define PT     68        // feature-major pitch for x_s/h_s/qkv_s/ho_s
#define PO     72        // obs tile pitch (row-major) — mma-fragment friendly
#define NTHREADS 256

typedef unsigned long long ull;

// ---- persistent repacked weights ----
__device__ __align__(16) float g_WihT[HDIM * 3 * HDIM];   // [k=64][j=192]
__device__ __align__(16) float g_WhhT[HDIM * 3 * HDIM];   // [k=64][j=192]
__device__ __align__(16) float g_qkvW[HDIM * 96];         // [k=64][q|k|v=96]
__device__ __align__(16) float g_decP[NACT * 96];         // [c][k]  (decW^T)
// encW packed in mma B-fragment order, tf32-rounded:
// [s=kstep 0..31][t=ntile 0..7][lane 0..31][2]
__device__ __align__(16) float g_encF[32 * 8 * 32 * 2];

__device__ __forceinline__ unsigned to_tf32(float x) {
    unsigned r; asm("cvt.rna.tf32.f32 %0, %1;" : "=r"(r) : "f"(x)); return r;
}

__global__ void setup_kernel(const float* __restrict__ encW,
                             const float* __restrict__ Wih,
                             const float* __restrict__ Whh,
                             const float* __restrict__ qW,
                             const float* __restrict__ kW,
                             const float* __restrict__ vW,
                             const float* __restrict__ decW)
{
    const int stride = gridDim.x * blockDim.x;
    const int t0 = blockIdx.x * blockDim.x + threadIdx.x;
    for (int idx = t0; idx < HDIM * 192; idx += stride) {
        int k = idx / 192, j = idx - k * 192;
        g_WihT[idx] = Wih[j * HDIM + k];
        g_WhhT[idx] = Whh[j * HDIM + k];
    }
    for (int idx = t0; idx < HDIM * 96; idx += stride) {
        int k = idx / 96, a = idx - k * 96;
        float v;
        if (a < 32)      v = qW[k * 32 + a];
        else if (a < 64) v = kW[k * 32 + (a - 32)];
        else             v = vW[k * 32 + (a - 64)];
        g_qkvW[idx] = v;
    }
    for (int idx = t0; idx < NACT * 96; idx += stride) {
        int c = idx / 96, k = idx - c * 96;
        g_decP[idx] = decW[k * NACT + c];
    }
    // encW -> B-fragment order (m16n8k8 tf32: b0 k=lane%4, b1 k=lane%4+4; col=lane/4)
    for (int idx = t0; idx < 32 * 8 * 32 * 2; idx += stride) {
        int p    = idx & 1;
        int lane = (idx >> 1) & 31;
        int t    = (idx >> 6) & 7;
        int s    = idx >> 9;
        int krow = s * 8 + (lane & 3) + (p ? 4 : 0);
        int col  = t * 8 + (lane >> 2);
        g_encF[idx] = __uint_as_float(to_tf32(encW[krow * HDIM + col]));
    }
}

// ---------------- f32x2 helpers ----------------
__device__ __forceinline__ void ffma2(ull& acc, ull a, ull b) {
    asm("fma.rn.f32x2 %0, %1, %2, %0;" : "+l"(acc) : "l"(a), "l"(b));
}
__device__ __forceinline__ ull pack2(float x) {
    ull d; unsigned xi = __float_as_uint(x);
    asm("mov.b64 %0, {%1, %1};" : "=l"(d) : "r"(xi));
    return d;
}
__device__ __forceinline__ ull pack_ab(float a, float b) {
    ull d;
    asm("mov.b64 %0, {%1, %2};" : "=l"(d) : "f"(a), "f"(b));
    return d;
}
__device__ __forceinline__ float2 unpack2(ull v) {
    float2 r;
    asm("mov.b64 {%0, %1}, %2;" : "=f"(r.x), "=f"(r.y) : "l"(v));
    return r;
}
__device__ __forceinline__ float hsum2(ull v) {
    float2 r = unpack2(v);
    return r.x + r.y;
}
__device__ __forceinline__ unsigned saddr(const void* p) {
    return (unsigned)__cvta_generic_to_shared(p);
}
__device__ __forceinline__ float tanh_fast(float x) {
    float r; asm("tanh.approx.f32 %0, %1;" : "=f"(r) : "f"(x)); return r;
}
__device__ __forceinline__ float sigmoid_fast(float s) {
    return fmaf(tanh_fast(0.5f * s), 0.5f, 0.5f);
}
__device__ __forceinline__ void mma_tf32(float d[4],
                                         unsigned a0, unsigned a1, unsigned a2, unsigned a3,
                                         unsigned b0, unsigned b1) {
    asm("mma.sync.aligned.m16n8k8.row.col.f32.tf32.tf32.f32 "
        "{%0,%1,%2,%3}, {%4,%5,%6,%7}, {%8,%9}, {%0,%1,%2,%3};"
        : "+f"(d[0]), "+f"(d[1]), "+f"(d[2]), "+f"(d[3])
        : "r"(a0), "r"(a1), "r"(a2), "r"(a3), "r"(b0), "r"(b1));
}

__global__ void __launch_bounds__(NTHREADS, 3)
fused_kernel(const float* __restrict__ obs,
             const float* __restrict__ hid,
             const float* __restrict__ encb,
             const float* __restrict__ bih,
             const float* __restrict__ bhh,
             const float* __restrict__ vb,
             const float* __restrict__ decb,
             float* __restrict__ outp,
             float* __restrict__ houtp)
{
    extern __shared__ float sm[];
    // regionA [0, 9216): obs double buffer (pitch PO) -> later ho_s (96*PT=6528)
    float* Abuf0 = sm;
    float* Abuf1 = sm + 4608;
    float* ho_s  = sm;                 // [96 feat][PT]
    // regionB [9216, 17920): x_s + h_s -> later qkv_s (96*PT=6528)
    float* x_s   = sm + 9216;          // [64 feat][PT]
    float* h_s   = sm + 13568;         // [64 feat][PT]
    float* qkv_s = sm + 9216;          // [96 feat][PT]

    const int tid  = threadIdx.x;
    const int trow = tid >> 4;
    const int tcol = tid & 15;
    const int r0 = trow * 4;
    const int c0 = tcol * 4;
    const int rowbase = blockIdx.x * BM;

    // ---- prefetch obs tile 0 via cp.async ----
    {
#pragma unroll
        for (int c = 0; c < 4; c++) {
            int chunk = tid + c * 256;
            int row = chunk >> 4, off = (chunk & 15) * 4;
            const float* src = obs + (size_t)(rowbase + row) * DIN + off;
            unsigned d = saddr(&Abuf0[row * PO + off]);
            asm volatile("cp.async.cg.shared.global [%0], [%1], 16;" :: "r"(d), "l"(src));
        }
        asm volatile("cp.async.commit_group;");
    }

    // ---- load hidden_state, transposed to feat-major h_s[k][r] ----
    for (int v = tid; v < BM * 16; v += NTHREADS) {
        int r = v >> 4, c4 = (v & 15) * 4;
        float4 t = *reinterpret_cast<const float4*>(&hid[(size_t)(rowbase + r) * HDIM + c4]);
        h_s[(c4 + 0) * PT + r] = t.x;
        h_s[(c4 + 1) * PT + r] = t.y;
        h_s[(c4 + 2) * PT + r] = t.z;
        h_s[(c4 + 3) * PT + r] = t.w;
    }

    // ---------------- encoder via tf32 mma: x = relu(obs @ enc_W + b) -------
    {
        const int w    = tid >> 5;        // warp 0..7
        const int lane = tid & 31;
        const int g    = lane >> 2;       // group id (row within tile)
        const int tg   = lane & 3;        // thread in group
        const int mb   = (w & 1) * 32;    // m block (rows)
        const int tnb  = (w >> 1) * 2;    // first n-tile index (cols = tnb*8)

        float d[2][2][4];
#pragma unroll
        for (int mt = 0; mt < 2; mt++)
#pragma unroll
            for (int nt = 0; nt < 2; nt++)
#pragma unroll
                for (int e = 0; e < 4; e++) d[mt][nt][e] = 0.f;

#pragma unroll
        for (int kt = 0; kt < 4; kt++) {
            __syncthreads();
            if (kt < 3) {
                float* dst = ((kt + 1) & 1) ? Abuf1 : Abuf0;
#pragma unroll
                for (int c = 0; c < 4; c++) {
                    int chunk = tid + c * 256;
                    int row = chunk >> 4, off = (chunk & 15) * 4;
                    const float* src = obs + (size_t)(rowbase + row) * DIN + (kt + 1) * 64 + off;
                    unsigned dsta = saddr(&dst[row * PO + off]);
                    asm volatile("cp.async.cg.shared.global [%0], [%1], 16;" :: "r"(dsta), "l"(src));
                }
                asm volatile("cp.async.commit_group;");
                asm volatile("cp.async.wait_group 1;");
            } else {
                asm volatile("cp.async.wait_group 0;");
            }
            __syncthreads();

            const float* Ac = (kt & 1) ? Abuf1 : Abuf0;
#pragma unroll
            for (int s = 0; s < 8; s++) {
                const int gs = kt * 8 + s;          // global k-step
                // B fragments for the two n-tiles (coalesced LDG.64, tf32 pre-rounded)
                const float2 bf0 = *reinterpret_cast<const float2*>(&g_encF[((gs * 8 + tnb + 0) * 32 + lane) * 2]);
                const float2 bf1 = *reinterpret_cast<const float2*>(&g_encF[((gs * 8 + tnb + 1) * 32 + lane) * 2]);
                unsigned b00 = __float_as_uint(bf0.x), b01 = __float_as_uint(bf0.y);
                unsigned b10 = __float_as_uint(bf1.x), b11 = __float_as_uint(bf1.y);
#pragma unroll
                for (int mt = 0; mt < 2; mt++) {
                    const int ar = mb + mt * 16 + g;
                    const int acl = s * 8 + tg;
                    unsigned a0 = to_tf32(Ac[ar * PO + acl]);
                    unsigned a1 = to_tf32(Ac[(ar + 8) * PO + acl]);
                    unsigned a2 = to_tf32(Ac[ar * PO + acl + 4]);
                    unsigned a3 = to_tf32(Ac[(ar + 8) * PO + acl + 4]);
                    mma_tf32(d[mt][0], a0, a1, a2, a3, b00, b01);
                    mma_tf32(d[mt][1], a0, a1, a2, a3, b10, b11);
                }
            }
        }

        // epilogue: bias + relu, scatter to feature-major x_s
#pragma unroll
        for (int nt = 0; nt < 2; nt++) {
            const int col0 = (tnb + nt) * 8 + tg * 2;
            const float b0 = encb[col0], b1 = encb[col0 + 1];
#pragma unroll
            for (int mt = 0; mt < 2; mt++) {
                const int row0 = mb + mt * 16 + g;
                x_s[col0 * PT + row0]           = fmaxf(d[mt][nt][0] + b0, 0.f);
                x_s[(col0 + 1) * PT + row0]     = fmaxf(d[mt][nt][1] + b1, 0.f);
                x_s[col0 * PT + row0 + 8]       = fmaxf(d[mt][nt][2] + b0, 0.f);
                x_s[(col0 + 1) * PT + row0 + 8] = fmaxf(d[mt][nt][3] + b1, 0.f);
            }
        }
    }
    __syncthreads();

    // ---------------- GRU cell: r -> rn -> n -> z+blend (min live regs) ----
    {
        ull carry[2][4];

        // ---- r gate (fused x+h) ----
        {
            ull acc[2][4] = {{0,0,0,0},{0,0,0,0}};
#pragma unroll 4
            for (int k = 0; k < HDIM; k++) {
                const ulonglong2 xv = *reinterpret_cast<const ulonglong2*>(&x_s[k * PT + r0]);
                const ulonglong2 hv = *reinterpret_cast<const ulonglong2*>(&h_s[k * PT + r0]);
                const float4 wx = *reinterpret_cast<const float4*>(&g_WihT[k * 192 + c0]);
                const float4 wh = *reinterpret_cast<const float4*>(&g_WhhT[k * 192 + c0]);
                const float wxv[4] = {wx.x, wx.y, wx.z, wx.w};
                const float whv[4] = {wh.x, wh.y, wh.z, wh.w};
#pragma unroll
                for (int j = 0; j < 4; j++) {
                    ull wxp = pack2(wxv[j]), whp = pack2(whv[j]);
                    ffma2(acc[0][j], xv.x, wxp); ffma2(acc[1][j], xv.y, wxp);
                    ffma2(acc[0][j], hv.x, whp); ffma2(acc[1][j], hv.y, whp);
                }
            }
            const float4 bx = *reinterpret_cast<const float4*>(&bih[c0]);
            const float4 bh = *reinterpret_cast<const float4*>(&bhh[c0]);
            const float bs[4] = {bx.x + bh.x, bx.y + bh.y, bx.z + bh.z, bx.w + bh.w};
#pragma unroll
            for (int p = 0; p < 2; p++)
#pragma unroll
                for (int j = 0; j < 4; j++) {
                    float2 v = unpack2(acc[p][j]);
                    carry[p][j] = pack_ab(sigmoid_fast(v.x + bs[j]), sigmoid_fast(v.y + bs[j]));
                }
        }

        // ---- hn pass: carry = rg * (h@Whh_n + bhh_n) ----
        {
            ull acc[2][4] = {{0,0,0,0},{0,0,0,0}};
#pragma unroll 4
            for (int k = 0; k < HDIM; k++) {
                const ulonglong2 hv = *reinterpret_cast<const ulonglong2*>(&h_s[k * PT + r0]);
                const float4 wh = *reinterpret_cast<const float4*>(&g_WhhT[k * 192 + 128 + c0]);
                const float whv[4] = {wh.x, wh.y, wh.z, wh.w};
#pragma unroll
                for (int j = 0; j < 4; j++) {
                    ull whp = pack2(whv[j]);
                    ffma2(acc[0][j], hv.x, whp); ffma2(acc[1][j], hv.y, whp);
                }
            }
            const float4 bh = *reinterpret_cast<const float4*>(&bhh[128 + c0]);
            const float bhv[4] = {bh.x, bh.y, bh.z, bh.w};
#pragma unroll
            for (int p = 0; p < 2; p++)
#pragma unroll
                for (int j = 0; j < 4; j++) {
                    float2 v = unpack2(acc[p][j]);
                    float2 r = unpack2(carry[p][j]);
                    carry[p][j] = pack_ab(r.x * (v.x + bhv[j]), r.y * (v.y + bhv[j]));
                }
        }

        // ---- xn pass: carry = tanh(x@Wih_n + bih_n + carry) ----
        {
            ull acc[2][4] = {{0,0,0,0},{0,0,0,0}};
#pragma unroll 4
            for (int k = 0; k < HDIM; k++) {
                const ulonglong2 xv = *reinterpret_cast<const ulonglong2*>(&x_s[k * PT + r0]);
                const float4 wx = *reinterpret_cast<const float4*>(&g_WihT[k * 192 + 128 + c0]);
                const float wxv[4] = {wx.x, wx.y, wx.z, wx.w};
#pragma unroll
                for (int j = 0; j < 4; j++) {
                    ull wxp = pack2(wxv[j]);
                    ffma2(acc[0][j], xv.x, wxp); ffma2(acc[1][j], xv.y, wxp);
                }
            }
            const float4 bx = *reinterpret_cast<const float4*>(&bih[128 + c0]);
            const float bxv[4] = {bx.x, bx.y, bx.z, bx.w};
#pragma unroll
            for (int p = 0; p < 2; p++)
#pragma unroll
                for (int j = 0; j < 4; j++) {
                    float2 xn = unpack2(acc[p][j]);
                    float2 rn = unpack2(carry[p][j]);
                    carry[p][j] = pack_ab(tanh_fast(xn.x + bxv[j] + rn.x),
                                          tanh_fast(xn.y + bxv[j] + rn.y));
                }
        }

        // ---- z gate (fused x+h) + blend + store ho_s ----
        {
            ull acc[2][4] = {{0,0,0,0},{0,0,0,0}};
#pragma unroll 4
            for (int k = 0; k < HDIM; k++) {
                const ulonglong2 xv = *reinterpret_cast<const ulonglong2*>(&x_s[k * PT + r0]);
                const ulonglong2 hv = *reinterpret_cast<const ulonglong2*>(&h_s[k * PT + r0]);
                const float4 wx = *reinterpret_cast<const float4*>(&g_WihT[k * 192 + 64 + c0]);
                const float4 wh = *reinterpret_cast<const float4*>(&g_WhhT[k * 192 + 64 + c0]);
                const float wxv[4] = {wx.x, wx.y, wx.z, wx.w};
                const float whv[4] = {wh.x, wh.y, wh.z, wh.w};
#pragma unroll
                for (int j = 0; j < 4; j++) {
                    ull wxp = pack2(wxv[j]), whp = pack2(whv[j]);
                    ffma2(acc[0][j], xv.x, wxp); ffma2(acc[1][j], xv.y, wxp);
                    ffma2(acc[0][j], hv.x, whp); ffma2(acc[1][j], hv.y, whp);
                }
            }
            const float4 bx = *reinterpret_cast<const float4*>(&bih[64 + c0]);
            const float4 bh = *reinterpret_cast<const float4*>(&bhh[64 + c0]);
            const float bs[4] = {bx.x + bh.x, bx.y + bh.y, bx.z + bh.z, bx.w + bh.w};
            __syncthreads();   // regionA: obs buffers dead; ho_s writes begin
#pragma unroll
            for (int p = 0; p < 2; p++)
#pragma unroll
                for (int j = 0; j < 4; j++) {
                    float2 v = unpack2(acc[p][j]);
                    float2 n = unpack2(carry[p][j]);
                    ull hp2 = *reinterpret_cast<const ull*>(&h_s[(c0 + j) * PT + r0 + 2 * p]);
                    float2 hp = unpack2(hp2);
                    float z0 = sigmoid_fast(v.x + bs[j]);
                    float z1 = sigmoid_fast(v.y + bs[j]);
                    float o0 = (1.f - z0) * n.x + z0 * hp.x;
                    float o1 = (1.f - z1) * n.y + z1 * hp.y;
                    *reinterpret_cast<ull*>(&ho_s[(c0 + j) * PT + r0 + 2 * p]) = pack_ab(o0, o1);
                }
        }
    }
    __syncthreads();

    // ---------------- q|k|v GEMM (N=96) + h_out writeback -------------------
    {
        for (int v = tid; v < BM * 16; v += NTHREADS) {
            int r = v >> 4, c4 = (v & 15) * 4;
            float4 t;
            t.x = ho_s[(c4 + 0) * PT + r];
            t.y = ho_s[(c4 + 1) * PT + r];
            t.z = ho_s[(c4 + 2) * PT + r];
            t.w = ho_s[(c4 + 3) * PT + r];
            *reinterpret_cast<float4*>(&houtp[(size_t)(rowbase + r) * HDIM + c4]) = t;
        }

        const int cq = tcol * 6;
        ull acc[2][6];
#pragma unroll
        for (int p = 0; p < 2; p++)
#pragma unroll
            for (int m = 0; m < 6; m++) acc[p][m] = 0;

#pragma unroll 4
        for (int k = 0; k < HDIM; k++) {
            const ulonglong2 hv = *reinterpret_cast<const ulonglong2*>(&ho_s[k * PT + r0]);
            const float2 w01 = *reinterpret_cast<const float2*>(&g_qkvW[k * 96 + cq]);
            const float2 w23 = *reinterpret_cast<const float2*>(&g_qkvW[k * 96 + cq + 2]);
            const float2 w45 = *reinterpret_cast<const float2*>(&g_qkvW[k * 96 + cq + 4]);
            const float wv[6] = {w01.x, w01.y, w23.x, w23.y, w45.x, w45.y};
#pragma unroll
            for (int m = 0; m < 6; m++) {
                ull wp = pack2(wv[m]);
                ffma2(acc[0][m], hv.x, wp);
                ffma2(acc[1][m], hv.y, wp);
            }
        }
        __syncthreads();   // regionB: x_s/h_s dead; qkv_s writes begin
#pragma unroll
        for (int p = 0; p < 2; p++)
#pragma unroll
            for (int m = 0; m < 6; m++) {
                int cg = cq + m;
                float2 v = unpack2(acc[p][m]);
                if (cg >= 64) {
                    float b = vb[cg - 64];
                    v.x = fmaxf(v.x + b, 0.f);
                    v.y = fmaxf(v.y + b, 0.f);
                }
                *reinterpret_cast<ull*>(&qkv_s[cg * PT + r0 + 2 * p]) = pack_ab(v.x, v.y);
            }
    }
    __syncthreads();

    // ---------------- exclude-self attention (packed over j-pairs) ----------
    if (tid < BM) {
        const int ii = tid & 7;
        const int base = tid & ~7;
        ull sp[4] = {0, 0, 0, 0};
#pragma unroll 8
        for (int a = 0; a < ADIM; a++) {
            ull qa = pack2(qkv_s[a * PT + tid]);
            const ulonglong2 k01 = *reinterpret_cast<const ulonglong2*>(&qkv_s[(32 + a) * PT + base]);
            const ulonglong2 k23 = *reinterpret_cast<const ulonglong2*>(&qkv_s[(32 + a) * PT + base + 4]);
            ffma2(sp[0], k01.x, qa); ffma2(sp[1], k01.y, qa);
            ffma2(sp[2], k23.x, qa); ffma2(sp[3], k23.y, qa);
        }
        float sc[NS];
#pragma unroll
        for (int jp = 0; jp < 4; jp++) {
            float2 v = unpack2(sp[jp]);
            sc[2 * jp]     = v.x * 0.17677669529663689f;
            sc[2 * jp + 1] = v.y * 0.17677669529663689f;
        }
        sc[ii] = -1e9f;
        float mx = -1e30f;
#pragma unroll
        for (int j = 0; j < NS; j++) mx = fmaxf(mx, sc[j]);
        float sum = 0.f;
#pragma unroll
        for (int j = 0; j < NS; j++) { sc[j] = __expf(sc[j] - mx); sum += sc[j]; }
        const float inv = __fdividef(1.f, sum);
        ull wp[4];
#pragma unroll
        for (int jp = 0; jp < 4; jp++)
            wp[jp] = pack_ab(sc[2 * jp] * inv, sc[2 * jp + 1] * inv);
#pragma unroll 8
        for (int a = 0; a < ADIM; a++) {
            const ulonglong2 v01 = *reinterpret_cast<const ulonglong2*>(&qkv_s[(64 + a) * PT + base]);
            const ulonglong2 v23 = *reinterpret_cast<const ulonglong2*>(&qkv_s[(64 + a) * PT + base + 4]);
            ull t = 0;
            ffma2(t, v01.x, wp[0]); ffma2(t, v01.y, wp[1]);
            ffma2(t, v23.x, wp[2]); ffma2(t, v23.y, wp[3]);
            ho_s[(64 + a) * PT + tid] = hsum2(t);
        }
    }
    __syncthreads();

    // ---------------- decoder: out = [h_out|xatt] @ decW + decb -------------
    for (int it = tid; it < 448; it += NTHREADS) {
        int pr = it & 31, c = it >> 5;
        ull acc = 0;
#pragma unroll 6
        for (int k4 = 0; k4 < 24; k4++) {
            const float4 wv = *reinterpret_cast<const float4*>(&g_decP[c * 96 + k4 * 4]);
            ull h0 = *reinterpret_cast<const ull*>(&ho_s[(k4 * 4 + 0) * PT + 2 * pr]);
            ull h1 = *reinterpret_cast<const ull*>(&ho_s[(k4 * 4 + 1) * PT + 2 * pr]);
            ull h2 = *reinterpret_cast<const ull*>(&ho_s[(k4 * 4 + 2) * PT + 2 * pr]);
            ull h3 = *reinterpret_cast<const ull*>(&ho_s[(k4 * 4 + 3) * PT + 2 * pr]);
            ffma2(acc, h0, pack2(wv.x));
            ffma2(acc, h1, pack2(wv.y));
            ffma2(acc, h2, pack2(wv.z));
            ffma2(acc, h3, pack2(wv.w));
        }
        float2 p = unpack2(acc);
        float b = decb[c];
        size_t r = (size_t)(rowbase + 2 * pr);
        outp[r * NACT + c]       = p.x + b;
        outp[(r + 1) * NACT + c] = p.y + b;
    }
}

extern "C" void kernel_launch(void* const* d_in, const int* in_sizes, int n_in,
                              void* d_out, int out_size)
{
    (void)in_sizes; (void)n_in; (void)out_size;
    const float* obs  = (const float*)d_in[0];
    const float* hid  = (const float*)d_in[1];
    const float* encW = (const float*)d_in[2];
    const float* encb = (const float*)d_in[3];
    const float* Wih  = (const float*)d_in[4];
    const float* Whh  = (const float*)d_in[5];
    const float* bih  = (const float*)d_in[6];
    const float* bhh  = (const float*)d_in[7];
    const float* qW   = (const float*)d_in[8];
    const float* kW   = (const float*)d_in[9];
    const float* vW   = (const float*)d_in[10];
    const float* vb   = (const float*)d_in[11];
    const float* decW = (const float*)d_in[12];
    const float* decb = (const float*)d_in[13];

    float* outp  = (float*)d_out;                 // [B, 14]
    float* houtp = outp + (size_t)BTOT * NACT;    // [B, 64]

    setup_kernel<<<64, 256>>>(encW, Wih, Whh, qW, kW, vW, decW);

    const int smem_bytes = 17920 * sizeof(float); // 71,680 B -> 3 CTAs/SM
    cudaFuncSetAttribute(fused_kernel,
                         cudaFuncAttributeMaxDynamicSharedMemorySize, smem_bytes);
    fused_kernel<<<BTOT / BM, NTHREADS, smem_bytes>>>(
        obs, hid, encb, bih, bhh, vb, decb, outp, houtp);
}